// round 1
// baseline (speedup 1.0000x reference)
#include <cuda_runtime.h>
#include <math.h>

#define Bb   256
#define NR   64
#define NW   64
#define NH   8
#define DK   64
#define Ee   512   /* NH*DK = NH*DV */
#define DIN  512
#define TOPKK 16
#define EPSF 1e-7f

// ---------------- device scratch (no cudaMalloc allowed) ----------------
__device__ float g_qp[Bb * NR * Ee];     // (b, r, h*64+e)
__device__ float g_kp[Bb * NW * Ee];     // (b, l, h*64+e)
__device__ float g_vsum[Bb * Ee];        // (b, e)
__device__ float g_attn[Bb * NR * NH];   // (b, r, h)
__device__ float g_F[Bb * NH * Ee];      // (b, h, o)
__device__ float g_G[Bb * NH * Ee];      // (b, h, o)

// ---------------- generic batched SGEMM: C = A @ W ----------------
// tiles: 128x128x8, 256 threads, 8x8 microtile. M,N multiples of 128, K mult of 8.
__global__ __launch_bounds__(256) void sgemm128(
    const float* __restrict__ A, long lda, long aBatch,
    const float* __restrict__ W, long ldw, long wBatch,
    float* __restrict__ C, long ldc, long cBatch,
    int K)
{
    __shared__ float As[8][128];
    __shared__ float Ws[8][128];
    long g = blockIdx.z;
    A += g * aBatch; W += g * wBatch; C += g * cBatch;
    long bm = (long)blockIdx.y * 128, bn = (long)blockIdx.x * 128;
    int tid = threadIdx.x;
    int arow = tid >> 1, acol = (tid & 1) * 4;
    int wrow = tid >> 5, wcol = (tid & 31) * 4;
    const float* Aptr = A + (bm + arow) * lda + acol;
    const float* Wptr = W + (long)wrow * ldw + bn + wcol;
    float acc[8][8];
#pragma unroll
    for (int i = 0; i < 8; i++)
#pragma unroll
        for (int j = 0; j < 8; j++) acc[i][j] = 0.f;
    int tr = (tid >> 4) * 8, tc = (tid & 15) * 8;
    for (int k0 = 0; k0 < K; k0 += 8) {
        float4 av = *(const float4*)Aptr;
        float4 wv = *(const float4*)Wptr;
        As[acol + 0][arow] = av.x;
        As[acol + 1][arow] = av.y;
        As[acol + 2][arow] = av.z;
        As[acol + 3][arow] = av.w;
        *(float4*)&Ws[wrow][wcol] = wv;
        __syncthreads();
#pragma unroll
        for (int kk = 0; kk < 8; kk++) {
            float4 a0 = *(const float4*)&As[kk][tr];
            float4 a1 = *(const float4*)&As[kk][tr + 4];
            float4 b0 = *(const float4*)&Ws[kk][tc];
            float4 b1 = *(const float4*)&Ws[kk][tc + 4];
            float ar[8] = {a0.x, a0.y, a0.z, a0.w, a1.x, a1.y, a1.z, a1.w};
            float br[8] = {b0.x, b0.y, b0.z, b0.w, b1.x, b1.y, b1.z, b1.w};
#pragma unroll
            for (int i = 0; i < 8; i++)
#pragma unroll
                for (int j = 0; j < 8; j++)
                    acc[i][j] = fmaf(ar[i], br[j], acc[i][j]);
        }
        __syncthreads();
        Aptr += 8;
        Wptr += 8 * ldw;
    }
#pragma unroll
    for (int i = 0; i < 8; i++) {
        float* cp = C + (bm + tr + i) * ldc + bn + tc;
        *(float4*)cp       = make_float4(acc[i][0], acc[i][1], acc[i][2], acc[i][3]);
        *(float4*)(cp + 4) = make_float4(acc[i][4], acc[i][5], acc[i][6], acc[i][7]);
    }
}

// ---------------- attention weights: scores -> max -> exp -> softmax_r -> top-k ----------------
// grid (NH, Bb), 256 threads. One block per (h,b).
__global__ __launch_bounds__(256) void attn_kernel()
{
    __shared__ float Qs[64][65];
    __shared__ float Ks[64][65];
    __shared__ float ev[64];
    __shared__ float sv[64];
    __shared__ float av[64];
    __shared__ float wv[64];
    __shared__ float dsh;
    int h = blockIdx.x, b = blockIdx.y;
    int t = threadIdx.x;

    for (int i = t; i < 64 * 64; i += 256) {
        int r = i >> 6, k = i & 63;
        Qs[r][k] = g_qp[((long)b * 64 + r) * 512 + h * 64 + k];
        Ks[r][k] = g_kp[((long)b * 64 + r) * 512 + h * 64 + k];
    }
    __syncthreads();

    // 4x4 microtile of the 64x64 score matrix
    int r0 = (t >> 4) * 4, l0 = (t & 15) * 4;
    float acc[4][4];
#pragma unroll
    for (int i = 0; i < 4; i++)
#pragma unroll
        for (int j = 0; j < 4; j++) acc[i][j] = 0.f;
    for (int k = 0; k < 64; k++) {
        float qv[4], kv[4];
#pragma unroll
        for (int i = 0; i < 4; i++) qv[i] = Qs[r0 + i][k];
#pragma unroll
        for (int j = 0; j < 4; j++) kv[j] = Ks[l0 + j][k];
#pragma unroll
        for (int i = 0; i < 4; i++)
#pragma unroll
            for (int j = 0; j < 4; j++)
                acc[i][j] = fmaf(qv[i], kv[j], acc[i][j]);
    }
    float mx[4];
#pragma unroll
    for (int i = 0; i < 4; i++) {
        float m = acc[i][0];
#pragma unroll
        for (int j = 1; j < 4; j++) m = fmaxf(m, acc[i][j]);
        mx[i] = m;
    }
    // reduce max over the 16 threads sharing r0 (contiguous half-warp)
#pragma unroll
    for (int s = 1; s < 16; s <<= 1) {
#pragma unroll
        for (int i = 0; i < 4; i++)
            mx[i] = fmaxf(mx[i], __shfl_xor_sync(0xffffffffu, mx[i], s));
    }
    if ((t & 15) == 0) {
#pragma unroll
        for (int i = 0; i < 4; i++)
            ev[r0 + i] = expf(mx[i] * 0.125f);   // exp(max(scores)/TEMP), TEMP = 8
    }
    __syncthreads();

    float e = 0.f, s = 0.f, a = 0.f, w = 0.f;
    if (t < 64) {
        e = ev[t];
        float m = -1e30f;
        for (int j = 0; j < 64; j++) m = fmaxf(m, ev[j]);
        s = expf(e - m);
        sv[t] = s;
    }
    __syncthreads();
    if (t < 64) {
        float sum = 0.f;
        for (int j = 0; j < 64; j++) sum += sv[j];
        a = s / sum;
        av[t] = a;
    }
    __syncthreads();
    if (t < 64) {
        int cnt = 0;
        for (int j = 0; j < 64; j++) {
            float o = av[j];
            cnt += (o > a) || (o == a && j < t);
        }
        if (cnt == TOPKK - 1) dsh = a;   // 16th largest (unique with index tiebreak)
    }
    __syncthreads();
    if (t < 64) {
        float delta = dsh + EPSF;
        w = fmaxf(a - delta, 0.f);
        wv[t] = w;
    }
    __syncthreads();
    if (t < 64) {
        float wsum = 0.f;
        for (int j = 0; j < 64; j++) wsum += wv[j];
        g_attn[((long)b * 64 + t) * 8 + h] = w / (wsum + EPSF);
    }
}

// ---------------- F/G: per-head vsum @ fc_w_h^T / gate_w_h^T ----------------
// grid (NH, 8 oTiles of 64, 4 bTiles of 64), 256 threads
__global__ __launch_bounds__(256) void fg_kernel(const float* __restrict__ fc_w,
                                                 const float* __restrict__ gate_w)
{
    __shared__ float wsm[64][65];   // [d][o]
    __shared__ float vssm[64][65];  // [d][b]
    int h = blockIdx.x;
    int o0 = blockIdx.y * 64;
    int b0 = blockIdx.z * 64;
    int t = threadIdx.x;

    for (int i = t; i < 64 * 16; i += 256) {
        int bi = i >> 4, d4 = (i & 15) * 4;
        float4 vv = *(const float4*)&g_vsum[((long)(b0 + bi)) * 512 + h * 64 + d4];
        vssm[d4 + 0][bi] = vv.x;
        vssm[d4 + 1][bi] = vv.y;
        vssm[d4 + 2][bi] = vv.z;
        vssm[d4 + 3][bi] = vv.w;
    }
    __syncthreads();

    int bb = (t >> 4) * 4, oo = (t & 15) * 4;
    for (int pass = 0; pass < 2; pass++) {
        const float* Wp = pass ? gate_w : fc_w;
        float* Out = pass ? g_G : g_F;
        for (int i = t; i < 64 * 16; i += 256) {
            int o = i >> 4, d4 = (i & 15) * 4;
            float4 wv4 = *(const float4*)&Wp[((long)(o0 + o)) * 512 + h * 64 + d4];
            wsm[d4 + 0][o] = wv4.x;
            wsm[d4 + 1][o] = wv4.y;
            wsm[d4 + 2][o] = wv4.z;
            wsm[d4 + 3][o] = wv4.w;
        }
        __syncthreads();
        float acc[4][4];
#pragma unroll
        for (int i = 0; i < 4; i++)
#pragma unroll
            for (int j = 0; j < 4; j++) acc[i][j] = 0.f;
        for (int d = 0; d < 64; d++) {
            float vv[4], ww[4];
#pragma unroll
            for (int i = 0; i < 4; i++) vv[i] = vssm[d][bb + i];
#pragma unroll
            for (int j = 0; j < 4; j++) ww[j] = wsm[d][oo + j];
#pragma unroll
            for (int i = 0; i < 4; i++)
#pragma unroll
                for (int j = 0; j < 4; j++)
                    acc[i][j] = fmaf(vv[i], ww[j], acc[i][j]);
        }
#pragma unroll
        for (int i = 0; i < 4; i++)
#pragma unroll
            for (int j = 0; j < 4; j++)
                Out[((long)(b0 + bb + i) * 8 + h) * 512 + o0 + oo + j] = acc[i][j];
        __syncthreads();
    }
}

// ---------------- final: out[b,r,o] = sigmoid(g)*tanh(f), 8-term combine ----------------
// grid (4 oTiles of 128, Bb), 256 threads
__global__ __launch_bounds__(256) void final_kernel(const float* __restrict__ fc_b,
                                                    const float* __restrict__ gate_b,
                                                    float* __restrict__ out)
{
    __shared__ float aw[64][8];
    __shared__ float Fs[8][128];
    __shared__ float Gs[8][128];
    __shared__ float fb[128], gb[128];
    int o0 = blockIdx.x * 128;
    int b = blockIdx.y;
    int t = threadIdx.x;

    for (int i = t; i < 512; i += 256)
        ((float*)aw)[i] = g_attn[(long)b * 512 + i];
    for (int i = t; i < 1024; i += 256) {
        int h = i >> 7, o = i & 127;
        Fs[h][o] = g_F[((long)b * 8 + h) * 512 + o0 + o];
        Gs[h][o] = g_G[((long)b * 8 + h) * 512 + o0 + o];
    }
    if (t < 128) {
        fb[t] = fc_b[o0 + t];
        gb[t] = gate_b[o0 + t];
    }
    __syncthreads();

    int oc = t & 31, rw = t >> 5;
    for (int r = rw; r < 64; r += 8) {
        float ah[8];
#pragma unroll
        for (int h = 0; h < 8; h++) ah[h] = aw[r][h];
        for (int ob = 0; ob < 128; ob += 32) {
            int o = ob + oc;
            float f = fb[o], g = gb[o];
#pragma unroll
            for (int h = 0; h < 8; h++) {
                f = fmaf(ah[h], Fs[h][o], f);
                g = fmaf(ah[h], Gs[h][o], g);
            }
            float sg = 1.f / (1.f + expf(-g));
            out[((long)b * 64 + r) * 512 + o0 + o] = sg * tanhf(f);
        }
    }
}

// ---------------- launch ----------------
extern "C" void kernel_launch(void* const* d_in, const int* in_sizes, int n_in,
                              void* d_out, int out_size)
{
    const float* q      = (const float*)d_in[0];
    const float* k      = (const float*)d_in[1];
    const float* v      = (const float*)d_in[2];
    const float* Wq     = (const float*)d_in[3];
    const float* Wk     = (const float*)d_in[4];
    const float* Wv     = (const float*)d_in[5];
    const float* fc_w   = (const float*)d_in[6];
    const float* fc_b   = (const float*)d_in[7];
    const float* gate_w = (const float*)d_in[8];
    const float* gate_b = (const float*)d_in[9];
    float* out = (float*)d_out;
    (void)in_sizes; (void)n_in; (void)out_size;

    void *qp_, *kp_, *vs_;
    cudaGetSymbolAddress(&qp_, g_qp);
    cudaGetSymbolAddress(&kp_, g_kp);
    cudaGetSymbolAddress(&vs_, g_vsum);
    float* qp = (float*)qp_;
    float* kp = (float*)kp_;
    float* vsum = (float*)vs_;

    // grouped projections: per n (64 groups): (256x512) @ (512x512)
    dim3 gProj(4, 2, 64);
    sgemm128<<<gProj, 256>>>(q, 32768, 512, Wq, 512, 262144, qp, 32768, 512, 512);
    sgemm128<<<gProj, 256>>>(k, 32768, 512, Wk, 512, 262144, kp, 32768, 512, 512);

    // vsum: (256 x 32768) @ (32768 x 512)
    dim3 gV(4, 2, 1);
    sgemm128<<<gV, 256>>>(v, 32768, 0, Wv, 512, 0, vsum, 512, 0, 32768);

    // attention weights per (h,b)
    attn_kernel<<<dim3(NH, Bb), 256>>>();

    // F/G factor matrices
    fg_kernel<<<dim3(NH, 8, 4), 256>>>(fc_w, gate_w);

    // final gated combine
    final_kernel<<<dim3(4, Bb), 256>>>(fc_b, gate_b, out);
}

// round 3
// speedup vs baseline: 8.0527x; 8.0527x over previous
#include <cuda_runtime.h>
#include <math.h>
#include <stdint.h>

#define Bb   256
#define NR   64
#define NW   64
#define NH   8
#define DK   64
#define Ee   512
#define TOPKK 16
#define EPSF 1e-7f

#define VSPLIT 32           /* split-K factor for vsum GEMM */
#define VSUM_ELEMS (Bb * Ee)

// ---------------- device scratch ----------------
__device__ float g_qp[Bb * NR * Ee];          // (b, r, h*64+e)
__device__ float g_kp[Bb * NW * Ee];          // (b, l, h*64+e)
__device__ float g_vpart[VSPLIT * VSUM_ELEMS];// split-K partials
__device__ float g_vsum[VSUM_ELEMS];          // (b, e)
__device__ float g_attn[Bb * NR * NH];        // (b, r, h)
__device__ float g_F[Bb * NH * Ee];           // (b, h, o)
__device__ float g_G[Bb * NH * Ee];           // (b, h, o)

__device__ __forceinline__ float tf32rna(float x) {
    uint32_t r;
    asm("cvt.rna.tf32.f32 %0, %1;" : "=r"(r) : "f"(x));
    return __uint_as_float(r);
}

// ---------------- 3xTF32 tensor-core GEMM: C = A @ W (fp32-accurate) ----------------
// BM=128 BN=128 BK=16, 256 threads (8 warps, 2x4), warp tile 64x32.
// batched (z = batch*splitK + kz). M,N mult of 128, kChunk mult of 16.
__global__ __launch_bounds__(256) void sgemm_tf32x3(
    const float* __restrict__ A, long lda, long aBatch,
    const float* __restrict__ W, long ldw, long wBatch,
    float* __restrict__ C, long ldc, long cBatch,
    int kIters, int splitK, long cSplit)
{
    __shared__ float As[2][128][20];   // [hi/lo][m][k], pitch 20 -> conflict-free frags
    __shared__ float Bs[2][16][136];   // [hi/lo][k][n], pitch 136 -> conflict-free frags

    int z = blockIdx.z;
    int batch = z / splitK;
    int kz = z - batch * splitK;
    long kBase = (long)kz * kIters * 16;
    A += batch * aBatch + kBase;
    W += batch * wBatch + kBase * ldw;
    C += batch * cBatch + (long)kz * cSplit;

    long bm = (long)blockIdx.y * 128;
    long bn = (long)blockIdx.x * 128;
    int tid = threadIdx.x;
    int lane = tid & 31, warp = tid >> 5;
    int wm0 = (warp >> 2) * 64;
    int wn0 = (warp & 3) * 32;
    int g = lane >> 2, tq = lane & 3;

    // loader mappings
    int arow0 = tid >> 2, acg = (tid & 3) * 4;       // + 64 rows for i=1
    int brow0 = tid >> 5, bcg = (tid & 31) * 4;      // + 8 rows for i=1

    float acc[4][4][4];
#pragma unroll
    for (int mi = 0; mi < 4; mi++)
#pragma unroll
        for (int ni = 0; ni < 4; ni++)
#pragma unroll
            for (int c = 0; c < 4; c++) acc[mi][ni][c] = 0.f;

    float4 ra[2], rb[2];
#pragma unroll
    for (int i = 0; i < 2; i++) {
        ra[i] = *(const float4*)(A + (bm + arow0 + i * 64) * lda + acg);
        rb[i] = *(const float4*)(W + (long)(brow0 + i * 8) * ldw + bn + bcg);
    }

#define STORE_TILE()                                                          \
    do {                                                                      \
        _Pragma("unroll")                                                     \
        for (int i = 0; i < 2; i++) {                                         \
            int r = arow0 + i * 64;                                           \
            float e[4] = {ra[i].x, ra[i].y, ra[i].z, ra[i].w};                \
            _Pragma("unroll")                                                 \
            for (int c = 0; c < 4; c++) {                                     \
                float hi = tf32rna(e[c]);                                     \
                As[0][r][acg + c] = hi;                                       \
                As[1][r][acg + c] = tf32rna(e[c] - hi);                       \
            }                                                                 \
            int kr = brow0 + i * 8;                                           \
            float f[4] = {rb[i].x, rb[i].y, rb[i].z, rb[i].w};                \
            _Pragma("unroll")                                                 \
            for (int c = 0; c < 4; c++) {                                     \
                float hi = tf32rna(f[c]);                                     \
                Bs[0][kr][bcg + c] = hi;                                      \
                Bs[1][kr][bcg + c] = tf32rna(f[c] - hi);                      \
            }                                                                 \
        }                                                                     \
    } while (0)

    STORE_TILE();
    __syncthreads();

    for (int kt = 0; kt < kIters; kt++) {
        bool hasNext = (kt + 1) < kIters;
        if (hasNext) {
            long ko = (long)(kt + 1) * 16;
#pragma unroll
            for (int i = 0; i < 2; i++) {
                ra[i] = *(const float4*)(A + (bm + arow0 + i * 64) * lda + ko + acg);
                rb[i] = *(const float4*)(W + (ko + brow0 + i * 8) * ldw + bn + bcg);
            }
        }
#pragma unroll
        for (int ks = 0; ks < 16; ks += 8) {
            uint32_t afh[4][4], afl[4][4];
#pragma unroll
            for (int mi = 0; mi < 4; mi++) {
                int m = wm0 + mi * 16 + g;
                afh[mi][0] = __float_as_uint(As[0][m][ks + tq]);
                afh[mi][1] = __float_as_uint(As[0][m + 8][ks + tq]);
                afh[mi][2] = __float_as_uint(As[0][m][ks + tq + 4]);
                afh[mi][3] = __float_as_uint(As[0][m + 8][ks + tq + 4]);
                afl[mi][0] = __float_as_uint(As[1][m][ks + tq]);
                afl[mi][1] = __float_as_uint(As[1][m + 8][ks + tq]);
                afl[mi][2] = __float_as_uint(As[1][m][ks + tq + 4]);
                afl[mi][3] = __float_as_uint(As[1][m + 8][ks + tq + 4]);
            }
            uint32_t bfh[4][2], bfl[4][2];
#pragma unroll
            for (int ni = 0; ni < 4; ni++) {
                int n = wn0 + ni * 8 + g;
                bfh[ni][0] = __float_as_uint(Bs[0][ks + tq][n]);
                bfh[ni][1] = __float_as_uint(Bs[0][ks + tq + 4][n]);
                bfl[ni][0] = __float_as_uint(Bs[1][ks + tq][n]);
                bfl[ni][1] = __float_as_uint(Bs[1][ks + tq + 4][n]);
            }
#define MMA(AF, BF, mi, ni)                                                   \
    asm volatile(                                                             \
        "mma.sync.aligned.m16n8k8.row.col.f32.tf32.tf32.f32 "                 \
        "{%0,%1,%2,%3}, {%4,%5,%6,%7}, {%8,%9}, {%0,%1,%2,%3};"               \
        : "+f"(acc[mi][ni][0]), "+f"(acc[mi][ni][1]),                         \
          "+f"(acc[mi][ni][2]), "+f"(acc[mi][ni][3])                          \
        : "r"(AF[mi][0]), "r"(AF[mi][1]), "r"(AF[mi][2]), "r"(AF[mi][3]),     \
          "r"(BF[ni][0]), "r"(BF[ni][1]))
#pragma unroll
            for (int mi = 0; mi < 4; mi++)
#pragma unroll
                for (int ni = 0; ni < 4; ni++) {
                    MMA(afl, bfh, mi, ni);   // lo*hi first (smallest terms)
                    MMA(afh, bfl, mi, ni);   // hi*lo
                    MMA(afh, bfh, mi, ni);   // hi*hi
                }
#undef MMA
        }
        if (hasNext) {
            __syncthreads();
            STORE_TILE();
            __syncthreads();
        }
    }
#undef STORE_TILE

    // epilogue
#pragma unroll
    for (int mi = 0; mi < 4; mi++) {
        long r0 = bm + wm0 + mi * 16 + g;
#pragma unroll
        for (int ni = 0; ni < 4; ni++) {
            long c0 = bn + wn0 + ni * 8 + 2 * tq;
            *(float2*)(C + r0 * ldc + c0) = make_float2(acc[mi][ni][0], acc[mi][ni][1]);
            *(float2*)(C + (r0 + 8) * ldc + c0) = make_float2(acc[mi][ni][2], acc[mi][ni][3]);
        }
    }
}

// ---------------- split-K reduction for vsum ----------------
__global__ __launch_bounds__(256) void reduce_vsum()
{
    int idx = blockIdx.x * 256 + threadIdx.x;
    float s = 0.f;
#pragma unroll
    for (int i = 0; i < VSPLIT; i++) s += g_vpart[(long)i * VSUM_ELEMS + idx];
    g_vsum[idx] = s;
}

// ---------------- attention weights ----------------
__global__ __launch_bounds__(256) void attn_kernel()
{
    __shared__ float Qs[64][65];
    __shared__ float Ks[64][65];
    __shared__ float ev[64];
    __shared__ float sv[64];
    __shared__ float av[64];
    __shared__ float wv[64];
    __shared__ float dsh;
    int h = blockIdx.x, b = blockIdx.y;
    int t = threadIdx.x;

    for (int i = t; i < 64 * 64; i += 256) {
        int r = i >> 6, k = i & 63;
        Qs[r][k] = g_qp[((long)b * 64 + r) * 512 + h * 64 + k];
        Ks[r][k] = g_kp[((long)b * 64 + r) * 512 + h * 64 + k];
    }
    __syncthreads();

    int r0 = (t >> 4) * 4, l0 = (t & 15) * 4;
    float acc[4][4];
#pragma unroll
    for (int i = 0; i < 4; i++)
#pragma unroll
        for (int j = 0; j < 4; j++) acc[i][j] = 0.f;
    for (int k = 0; k < 64; k++) {
        float qv[4], kv[4];
#pragma unroll
        for (int i = 0; i < 4; i++) qv[i] = Qs[r0 + i][k];
#pragma unroll
        for (int j = 0; j < 4; j++) kv[j] = Ks[l0 + j][k];
#pragma unroll
        for (int i = 0; i < 4; i++)
#pragma unroll
            for (int j = 0; j < 4; j++)
                acc[i][j] = fmaf(qv[i], kv[j], acc[i][j]);
    }
    float mx[4];
#pragma unroll
    for (int i = 0; i < 4; i++) {
        float m = acc[i][0];
#pragma unroll
        for (int j = 1; j < 4; j++) m = fmaxf(m, acc[i][j]);
        mx[i] = m;
    }
#pragma unroll
    for (int s = 1; s < 16; s <<= 1) {
#pragma unroll
        for (int i = 0; i < 4; i++)
            mx[i] = fmaxf(mx[i], __shfl_xor_sync(0xffffffffu, mx[i], s));
    }
    if ((t & 15) == 0) {
#pragma unroll
        for (int i = 0; i < 4; i++)
            ev[r0 + i] = expf(mx[i] * 0.125f);
    }
    __syncthreads();

    float e = 0.f, s = 0.f, a = 0.f, w = 0.f;
    if (t < 64) {
        e = ev[t];
        float m = -1e30f;
        for (int j = 0; j < 64; j++) m = fmaxf(m, ev[j]);
        s = expf(e - m);
        sv[t] = s;
    }
    __syncthreads();
    if (t < 64) {
        float sum = 0.f;
        for (int j = 0; j < 64; j++) sum += sv[j];
        a = s / sum;
        av[t] = a;
    }
    __syncthreads();
    if (t < 64) {
        int cnt = 0;
        for (int j = 0; j < 64; j++) {
            float o = av[j];
            cnt += (o > a) || (o == a && j < t);
        }
        if (cnt == TOPKK - 1) dsh = a;
    }
    __syncthreads();
    if (t < 64) {
        float delta = dsh + EPSF;
        w = fmaxf(a - delta, 0.f);
        wv[t] = w;
    }
    __syncthreads();
    if (t < 64) {
        float wsum = 0.f;
        for (int j = 0; j < 64; j++) wsum += wv[j];
        g_attn[((long)b * 64 + t) * 8 + h] = w / (wsum + EPSF);
    }
}

// ---------------- F/G factor matrices ----------------
__global__ __launch_bounds__(256) void fg_kernel(const float* __restrict__ fc_w,
                                                 const float* __restrict__ gate_w)
{
    __shared__ float wsm[64][65];
    __shared__ float vssm[64][65];
    int h = blockIdx.x;
    int o0 = blockIdx.y * 64;
    int b0 = blockIdx.z * 64;
    int t = threadIdx.x;

    for (int i = t; i < 64 * 16; i += 256) {
        int bi = i >> 4, d4 = (i & 15) * 4;
        float4 vv = *(const float4*)&g_vsum[((long)(b0 + bi)) * 512 + h * 64 + d4];
        vssm[d4 + 0][bi] = vv.x;
        vssm[d4 + 1][bi] = vv.y;
        vssm[d4 + 2][bi] = vv.z;
        vssm[d4 + 3][bi] = vv.w;
    }
    __syncthreads();

    int bb = (t >> 4) * 4, oo = (t & 15) * 4;
    for (int pass = 0; pass < 2; pass++) {
        const float* Wp = pass ? gate_w : fc_w;
        float* Out = pass ? g_G : g_F;
        for (int i = t; i < 64 * 16; i += 256) {
            int o = i >> 4, d4 = (i & 15) * 4;
            float4 wv4 = *(const float4*)&Wp[((long)(o0 + o)) * 512 + h * 64 + d4];
            wsm[d4 + 0][o] = wv4.x;
            wsm[d4 + 1][o] = wv4.y;
            wsm[d4 + 2][o] = wv4.z;
            wsm[d4 + 3][o] = wv4.w;
        }
        __syncthreads();
        float acc[4][4];
#pragma unroll
        for (int i = 0; i < 4; i++)
#pragma unroll
            for (int j = 0; j < 4; j++) acc[i][j] = 0.f;
        for (int d = 0; d < 64; d++) {
            float vv[4], ww[4];
#pragma unroll
            for (int i = 0; i < 4; i++) vv[i] = vssm[d][bb + i];
#pragma unroll
            for (int j = 0; j < 4; j++) ww[j] = wsm[d][oo + j];
#pragma unroll
            for (int i = 0; i < 4; i++)
#pragma unroll
                for (int j = 0; j < 4; j++)
                    acc[i][j] = fmaf(vv[i], ww[j], acc[i][j]);
        }
#pragma unroll
        for (int i = 0; i < 4; i++)
#pragma unroll
            for (int j = 0; j < 4; j++)
                Out[((long)(b0 + bb + i) * 8 + h) * 512 + o0 + oo + j] = acc[i][j];
        __syncthreads();
    }
}

// ---------------- final gated combine ----------------
__global__ __launch_bounds__(256) void final_kernel(const float* __restrict__ fc_b,
                                                    const float* __restrict__ gate_b,
                                                    float* __restrict__ out)
{
    __shared__ float aw[64][8];
    __shared__ float Fs[8][128];
    __shared__ float Gs[8][128];
    __shared__ float fb[128], gb[128];
    int o0 = blockIdx.x * 128;
    int b = blockIdx.y;
    int t = threadIdx.x;

    for (int i = t; i < 512; i += 256)
        ((float*)aw)[i] = g_attn[(long)b * 512 + i];
    for (int i = t; i < 1024; i += 256) {
        int h = i >> 7, o = i & 127;
        Fs[h][o] = g_F[((long)b * 8 + h) * 512 + o0 + o];
        Gs[h][o] = g_G[((long)b * 8 + h) * 512 + o0 + o];
    }
    if (t < 128) {
        fb[t] = fc_b[o0 + t];
        gb[t] = gate_b[o0 + t];
    }
    __syncthreads();

    int oc = t & 31, rw = t >> 5;
    for (int r = rw; r < 64; r += 8) {
        float ah[8];
#pragma unroll
        for (int h = 0; h < 8; h++) ah[h] = aw[r][h];
        for (int ob = 0; ob < 128; ob += 32) {
            int o = ob + oc;
            float f = fb[o], g = gb[o];
#pragma unroll
            for (int h = 0; h < 8; h++) {
                f = fmaf(ah[h], Fs[h][o], f);
                g = fmaf(ah[h], Gs[h][o], g);
            }
            float sg = 1.f / (1.f + expf(-g));
            out[((long)b * 64 + r) * 512 + o0 + o] = sg * tanhf(f);
        }
    }
}

// ---------------- launch ----------------
extern "C" void kernel_launch(void* const* d_in, const int* in_sizes, int n_in,
                              void* d_out, int out_size)
{
    const float* q      = (const float*)d_in[0];
    const float* k      = (const float*)d_in[1];
    const float* v      = (const float*)d_in[2];
    const float* Wq     = (const float*)d_in[3];
    const float* Wk     = (const float*)d_in[4];
    const float* Wv     = (const float*)d_in[5];
    const float* fc_w   = (const float*)d_in[6];
    const float* fc_b   = (const float*)d_in[7];
    const float* gate_w = (const float*)d_in[8];
    const float* gate_b = (const float*)d_in[9];
    float* out = (float*)d_out;
    (void)in_sizes; (void)n_in; (void)out_size;

    void *qp_, *kp_, *vp_;
    cudaGetSymbolAddress(&qp_, g_qp);
    cudaGetSymbolAddress(&kp_, g_kp);
    cudaGetSymbolAddress(&vp_, g_vpart);
    float* qp = (float*)qp_;
    float* kp = (float*)kp_;
    float* vpart = (float*)vp_;

    // grouped projections: 64 groups of (256x512)@(512x512), 3xTF32 tensor cores
    dim3 gProj(4, 2, 64);
    sgemm_tf32x3<<<gProj, 256>>>(q, 32768, 512, Wq, 512, 262144, qp, 32768, 512,
                                 32, 1, 0);
    sgemm_tf32x3<<<gProj, 256>>>(k, 32768, 512, Wk, 512, 262144, kp, 32768, 512,
                                 32, 1, 0);

    // vsum: (256 x 32768) @ (32768 x 512), split-K=32 (each chunk K=1024)
    dim3 gV(4, 2, VSPLIT);
    sgemm_tf32x3<<<gV, 256>>>(v, 32768, 0, Wv, 512, 0, vpart, 512, 0,
                              64, VSPLIT, VSUM_ELEMS);
    reduce_vsum<<<Bb * Ee / 256, 256>>>();

    attn_kernel<<<dim3(NH, Bb), 256>>>();
    fg_kernel<<<dim3(NH, 8, 4), 256>>>(fc_w, gate_w);
    final_kernel<<<dim3(4, Bb), 256>>>(fc_b, gate_b, out);
}

// round 4
// speedup vs baseline: 9.8002x; 1.2170x over previous
#include <cuda_runtime.h>
#include <math.h>
#include <stdint.h>

#define Bb   256
#define NR   64
#define NW   64
#define NH   8
#define Ee   512
#define TOPKK 16
#define EPSF 1e-7f

#define VSPLIT 32
#define VSUM_ELEMS (Bb * Ee)

// smem geometry for GEMM (floats)
#define APITCH 20
#define BPITCH 132
#define ASZ (128 * APITCH)          /* 2560 */
#define BSZ (16 * BPITCH)           /* 2112 */
#define BUFSZ (2 * ASZ + 2 * BSZ)   /* 9344 */
#define SMEM_BYTES (2 * BUFSZ * 4)  /* 74752 */

// ---------------- device scratch ----------------
__device__ float g_qp[Bb * NR * Ee];
__device__ float g_kp[Bb * NW * Ee];
__device__ float g_vpart[VSPLIT * VSUM_ELEMS];
__device__ float g_vsum[VSUM_ELEMS];
__device__ float g_attn[Bb * NR * NH];
__device__ float g_F[Bb * NH * Ee];
__device__ float g_G[Bb * NH * Ee];

__device__ __forceinline__ float tf32rna(float x) {
    uint32_t r;
    asm("cvt.rna.tf32.f32 %0, %1;" : "=r"(r) : "f"(x));
    return __uint_as_float(r);
}

// ---------------- 3xTF32 pipelined GEMM: C = A @ W ----------------
// BM=128 BN=128 BK=16, 256 threads, warp tile 64x32. Double-buffered smem.
// z-dispatch: z < zSplit uses set0 (A0,W0,C0) else set1. batch/splitK as before.
__global__ __launch_bounds__(256) void sgemm_tf32x3(
    const float* __restrict__ A0, const float* __restrict__ W0, float* __restrict__ C0,
    const float* __restrict__ A1, const float* __restrict__ W1, float* __restrict__ C1,
    long lda, long aBatch, long ldw, long wBatch, long ldc, long cBatch,
    int kIters, int splitK, long cSplit, int zSplit)
{
    extern __shared__ float sm[];

    int z = blockIdx.z;
    const float* A; const float* W; float* C;
    if (z < zSplit) { A = A0; W = W0; C = C0; }
    else            { A = A1; W = W1; C = C1; z -= zSplit; }
    int batch = z / splitK;
    int kz = z - batch * splitK;
    long kBase = (long)kz * kIters * 16;
    A += batch * aBatch + kBase;
    W += batch * wBatch + kBase * ldw;
    C += batch * cBatch + (long)kz * cSplit;

    long bm = (long)blockIdx.y * 128;
    long bn = (long)blockIdx.x * 128;
    int tid = threadIdx.x;
    int lane = tid & 31, warp = tid >> 5;
    int wm0 = (warp >> 2) * 64;
    int wn0 = (warp & 3) * 32;
    int g = lane >> 2, tq = lane & 3;

    int arow0 = tid >> 2, acg = (tid & 3) * 4;
    int brow0 = tid >> 5, bcg = (tid & 31) * 4;

    const float* Aload = A + (bm + arow0) * lda + acg;
    const float* Wload = W + (long)brow0 * ldw + bn + bcg;

    float acc[4][4][4];
#pragma unroll
    for (int mi = 0; mi < 4; mi++)
#pragma unroll
        for (int ni = 0; ni < 4; ni++)
#pragma unroll
            for (int c = 0; c < 4; c++) acc[mi][ni][c] = 0.f;

    float4 ra[2], rb[2];

#define LOADG(ko)                                                        \
    do {                                                                 \
        ra[0] = *(const float4*)(Aload + (ko));                          \
        ra[1] = *(const float4*)(Aload + 64 * lda + (ko));               \
        rb[0] = *(const float4*)(Wload + (long)(ko) * ldw);              \
        rb[1] = *(const float4*)(Wload + ((long)(ko) + 8) * ldw);        \
    } while (0)

#define STORE(buf)                                                       \
    do {                                                                 \
        float* Ahi = sm + (buf) * BUFSZ;                                 \
        float* Alo = Ahi + ASZ;                                          \
        float* Bhi = sm + (buf) * BUFSZ + 2 * ASZ;                       \
        float* Blo = Bhi + BSZ;                                          \
        _Pragma("unroll")                                                \
        for (int i = 0; i < 2; i++) {                                    \
            int r = arow0 + i * 64;                                      \
            float4 hv, lv;                                               \
            hv.x = tf32rna(ra[i].x); lv.x = tf32rna(ra[i].x - hv.x);     \
            hv.y = tf32rna(ra[i].y); lv.y = tf32rna(ra[i].y - hv.y);     \
            hv.z = tf32rna(ra[i].z); lv.z = tf32rna(ra[i].z - hv.z);     \
            hv.w = tf32rna(ra[i].w); lv.w = tf32rna(ra[i].w - hv.w);     \
            *(float4*)&Ahi[r * APITCH + acg] = hv;                       \
            *(float4*)&Alo[r * APITCH + acg] = lv;                       \
            int kr = brow0 + i * 8;                                      \
            hv.x = tf32rna(rb[i].x); lv.x = tf32rna(rb[i].x - hv.x);     \
            hv.y = tf32rna(rb[i].y); lv.y = tf32rna(rb[i].y - hv.y);     \
            hv.z = tf32rna(rb[i].z); lv.z = tf32rna(rb[i].z - hv.z);     \
            hv.w = tf32rna(rb[i].w); lv.w = tf32rna(rb[i].w - hv.w);     \
            *(float4*)&Bhi[kr * BPITCH + bcg] = hv;                      \
            *(float4*)&Blo[kr * BPITCH + bcg] = lv;                      \
        }                                                                \
    } while (0)

    LOADG(0);
    STORE(0);
    if (kIters > 1) LOADG(16);
    __syncthreads();

    for (int kt = 0; kt < kIters; kt++) {
        int cur = kt & 1;
        if (kt + 1 < kIters) {
            STORE(cur ^ 1);
            if (kt + 2 < kIters) LOADG((long)(kt + 2) * 16);
        }
        const float* Ahi = sm + cur * BUFSZ;
        const float* Alo = Ahi + ASZ;
        const float* Bhi = sm + cur * BUFSZ + 2 * ASZ;
        const float* Blo = Bhi + BSZ;
#pragma unroll
        for (int ks = 0; ks < 16; ks += 8) {
            float afh[4][4], afl[4][4];
#pragma unroll
            for (int mi = 0; mi < 4; mi++) {
                int m = wm0 + mi * 16 + g;
                afh[mi][0] = Ahi[m * APITCH + ks + tq];
                afh[mi][1] = Ahi[(m + 8) * APITCH + ks + tq];
                afh[mi][2] = Ahi[m * APITCH + ks + tq + 4];
                afh[mi][3] = Ahi[(m + 8) * APITCH + ks + tq + 4];
                afl[mi][0] = Alo[m * APITCH + ks + tq];
                afl[mi][1] = Alo[(m + 8) * APITCH + ks + tq];
                afl[mi][2] = Alo[m * APITCH + ks + tq + 4];
                afl[mi][3] = Alo[(m + 8) * APITCH + ks + tq + 4];
            }
            float bfh[4][2], bfl[4][2];
#pragma unroll
            for (int ni = 0; ni < 4; ni++) {
                int n = wn0 + ni * 8 + g;
                bfh[ni][0] = Bhi[(ks + tq) * BPITCH + n];
                bfh[ni][1] = Bhi[(ks + tq + 4) * BPITCH + n];
                bfl[ni][0] = Blo[(ks + tq) * BPITCH + n];
                bfl[ni][1] = Blo[(ks + tq + 4) * BPITCH + n];
            }
#define MMA(AF, BF, mi, ni)                                                   \
    asm volatile(                                                             \
        "mma.sync.aligned.m16n8k8.row.col.f32.tf32.tf32.f32 "                 \
        "{%0,%1,%2,%3}, {%4,%5,%6,%7}, {%8,%9}, {%0,%1,%2,%3};"               \
        : "+f"(acc[mi][ni][0]), "+f"(acc[mi][ni][1]),                         \
          "+f"(acc[mi][ni][2]), "+f"(acc[mi][ni][3])                          \
        : "r"(__float_as_uint(AF[mi][0])), "r"(__float_as_uint(AF[mi][1])),   \
          "r"(__float_as_uint(AF[mi][2])), "r"(__float_as_uint(AF[mi][3])),   \
          "r"(__float_as_uint(BF[ni][0])), "r"(__float_as_uint(BF[ni][1])))
#pragma unroll
            for (int mi = 0; mi < 4; mi++)
#pragma unroll
                for (int ni = 0; ni < 4; ni++) {
                    MMA(afl, bfh, mi, ni);
                    MMA(afh, bfl, mi, ni);
                    MMA(afh, bfh, mi, ni);
                }
#undef MMA
        }
        __syncthreads();
    }
#undef LOADG
#undef STORE

#pragma unroll
    for (int mi = 0; mi < 4; mi++) {
        long r0 = bm + wm0 + mi * 16 + g;
#pragma unroll
        for (int ni = 0; ni < 4; ni++) {
            long c0 = bn + wn0 + ni * 8 + 2 * tq;
            *(float2*)(C + r0 * ldc + c0) = make_float2(acc[mi][ni][0], acc[mi][ni][1]);
            *(float2*)(C + (r0 + 8) * ldc + c0) = make_float2(acc[mi][ni][2], acc[mi][ni][3]);
        }
    }
}

// ---------------- split-K reduction for vsum (float4) ----------------
__global__ __launch_bounds__(256) void reduce_vsum()
{
    int idx = (blockIdx.x * 256 + threadIdx.x) * 4;
    float4 s = make_float4(0.f, 0.f, 0.f, 0.f);
#pragma unroll
    for (int i = 0; i < VSPLIT; i++) {
        float4 p = *(const float4*)&g_vpart[(long)i * VSUM_ELEMS + idx];
        s.x += p.x; s.y += p.y; s.z += p.z; s.w += p.w;
    }
    *(float4*)&g_vsum[idx] = s;
}

// ---------------- attention weights ----------------
__global__ __launch_bounds__(256) void attn_kernel()
{
    __shared__ float Qs[64][65];
    __shared__ float Kst[64][68];   // [k][l]
    __shared__ float ev[64], av[64], wv[64];
    __shared__ float red[2], red2[2];
    __shared__ int cntS[4][64];
    __shared__ float dsh;
    int h = blockIdx.x, b = blockIdx.y;
    int t = threadIdx.x;
    int lane = t & 31, wid = t >> 5;

    const float* qpB = g_qp + (long)b * 64 * 512 + h * 64;
    const float* kpB = g_kp + (long)b * 64 * 512 + h * 64;
    for (int i = t; i < 4096; i += 256) {
        int r = i >> 6, k = i & 63;
        Qs[r][k] = qpB[(long)r * 512 + k];
        Kst[k][r] = kpB[(long)r * 512 + k];
    }
    __syncthreads();

    int r0 = (t >> 4) * 4, l0 = (t & 15) * 4;
    float acc[4][4];
#pragma unroll
    for (int i = 0; i < 4; i++)
#pragma unroll
        for (int j = 0; j < 4; j++) acc[i][j] = 0.f;
    for (int k = 0; k < 64; k++) {
        float4 kv = *(const float4*)&Kst[k][l0];
#pragma unroll
        for (int i = 0; i < 4; i++) {
            float qv = Qs[r0 + i][k];
            acc[i][0] = fmaf(qv, kv.x, acc[i][0]);
            acc[i][1] = fmaf(qv, kv.y, acc[i][1]);
            acc[i][2] = fmaf(qv, kv.z, acc[i][2]);
            acc[i][3] = fmaf(qv, kv.w, acc[i][3]);
        }
    }
    float mx[4];
#pragma unroll
    for (int i = 0; i < 4; i++) {
        float m = acc[i][0];
#pragma unroll
        for (int j = 1; j < 4; j++) m = fmaxf(m, acc[i][j]);
        mx[i] = m;
    }
#pragma unroll
    for (int s = 1; s < 16; s <<= 1) {
#pragma unroll
        for (int i = 0; i < 4; i++)
            mx[i] = fmaxf(mx[i], __shfl_xor_sync(0xffffffffu, mx[i], s));
    }
    if ((t & 15) == 0) {
#pragma unroll
        for (int i = 0; i < 4; i++)
            ev[r0 + i] = expf(mx[i] * 0.125f);
    }
    __syncthreads();

    // softmax over the 64 r's (threads 0..63 = warps 0,1)
    if (t < 64) {
        float m = ev[t];
#pragma unroll
        for (int s = 16; s > 0; s >>= 1) m = fmaxf(m, __shfl_xor_sync(0xffffffffu, m, s));
        if (lane == 0) red[wid] = m;
    }
    __syncthreads();
    if (t < 64) {
        float m = fmaxf(red[0], red[1]);
        float sx = expf(ev[t] - m);
        av[t] = sx;
        float ss = sx;
#pragma unroll
        for (int s = 16; s > 0; s >>= 1) ss += __shfl_xor_sync(0xffffffffu, ss, s);
        if (lane == 0) red2[wid] = ss;
    }
    __syncthreads();
    if (t < 64) av[t] = av[t] / (red2[0] + red2[1]);
    __syncthreads();

    // rank count (distributed 4-way)
    {
        int r = t & 63, part = t >> 6;
        float ar = av[r];
        int cnt = 0;
        int j0 = part * 16;
#pragma unroll
        for (int j = 0; j < 16; j++) {
            float o = av[j0 + j];
            cnt += (o > ar) || (o == ar && (j0 + j) < r);
        }
        cntS[part][r] = cnt;
    }
    __syncthreads();
    if (t < 64) {
        int cnt = cntS[0][t] + cntS[1][t] + cntS[2][t] + cntS[3][t];
        if (cnt == TOPKK - 1) dsh = av[t];
    }
    __syncthreads();
    if (t < 64) {
        float w = fmaxf(av[t] - (dsh + EPSF), 0.f);
        wv[t] = w;
        float ws = w;
#pragma unroll
        for (int s = 16; s > 0; s >>= 1) ws += __shfl_xor_sync(0xffffffffu, ws, s);
        if (lane == 0) red[wid] = ws;
    }
    __syncthreads();
    if (t < 64)
        g_attn[((long)b * 64 + t) * 8 + h] = wv[t] / (red[0] + red[1] + EPSF);
}

// ---------------- F/G factor matrices ----------------
__global__ __launch_bounds__(256) void fg_kernel(const float* __restrict__ fc_w,
                                                 const float* __restrict__ gate_w)
{
    __shared__ float wsm[64][65];
    __shared__ float vssm[64][65];
    int h = blockIdx.x;
    int o0 = blockIdx.y * 64;
    int b0 = blockIdx.z * 64;
    int t = threadIdx.x;

    for (int i = t; i < 64 * 16; i += 256) {
        int bi = i >> 4, d4 = (i & 15) * 4;
        float4 vv = *(const float4*)&g_vsum[((long)(b0 + bi)) * 512 + h * 64 + d4];
        vssm[d4 + 0][bi] = vv.x;
        vssm[d4 + 1][bi] = vv.y;
        vssm[d4 + 2][bi] = vv.z;
        vssm[d4 + 3][bi] = vv.w;
    }
    __syncthreads();

    int bb = (t >> 4) * 4, oo = (t & 15) * 4;
    for (int pass = 0; pass < 2; pass++) {
        const float* Wp = pass ? gate_w : fc_w;
        float* Out = pass ? g_G : g_F;
        for (int i = t; i < 64 * 16; i += 256) {
            int o = i >> 4, d4 = (i & 15) * 4;
            float4 wv4 = *(const float4*)&Wp[((long)(o0 + o)) * 512 + h * 64 + d4];
            wsm[d4 + 0][o] = wv4.x;
            wsm[d4 + 1][o] = wv4.y;
            wsm[d4 + 2][o] = wv4.z;
            wsm[d4 + 3][o] = wv4.w;
        }
        __syncthreads();
        float acc[4][4];
#pragma unroll
        for (int i = 0; i < 4; i++)
#pragma unroll
            for (int j = 0; j < 4; j++) acc[i][j] = 0.f;
        for (int d = 0; d < 64; d++) {
            float vv[4], ww[4];
#pragma unroll
            for (int i = 0; i < 4; i++) vv[i] = vssm[d][bb + i];
#pragma unroll
            for (int j = 0; j < 4; j++) ww[j] = wsm[d][oo + j];
#pragma unroll
            for (int i = 0; i < 4; i++)
#pragma unroll
                for (int j = 0; j < 4; j++)
                    acc[i][j] = fmaf(vv[i], ww[j], acc[i][j]);
        }
#pragma unroll
        for (int i = 0; i < 4; i++)
#pragma unroll
            for (int j = 0; j < 4; j++)
                Out[((long)(b0 + bb + i) * 8 + h) * 512 + o0 + oo + j] = acc[i][j];
        __syncthreads();
    }
}

// ---------------- final gated combine ----------------
__global__ __launch_bounds__(256) void final_kernel(const float* __restrict__ fc_b,
                                                    const float* __restrict__ gate_b,
                                                    float* __restrict__ out)
{
    __shared__ float aw[64][8];
    __shared__ float Fs[8][128];
    __shared__ float Gs[8][128];
    __shared__ float fb[128], gb[128];
    int o0 = blockIdx.x * 128;
    int b = blockIdx.y;
    int t = threadIdx.x;

    for (int i = t; i < 512; i += 256)
        ((float*)aw)[i] = g_attn[(long)b * 512 + i];
    for (int i = t; i < 1024; i += 256) {
        int h = i >> 7, o = i & 127;
        Fs[h][o] = g_F[((long)b * 8 + h) * 512 + o0 + o];
        Gs[h][o] = g_G[((long)b * 8 + h) * 512 + o0 + o];
    }
    if (t < 128) {
        fb[t] = fc_b[o0 + t];
        gb[t] = gate_b[o0 + t];
    }
    __syncthreads();

    int oc = t & 31, rw = t >> 5;
    for (int r = rw; r < 64; r += 8) {
        float ah[8];
#pragma unroll
        for (int h = 0; h < 8; h++) ah[h] = aw[r][h];
        for (int ob = 0; ob < 128; ob += 32) {
            int o = ob + oc;
            float f = fb[o], g = gb[o];
#pragma unroll
            for (int h = 0; h < 8; h++) {
                f = fmaf(ah[h], Fs[h][o], f);
                g = fmaf(ah[h], Gs[h][o], g);
            }
            float sg = 1.f / (1.f + expf(-g));
            out[((long)b * 64 + r) * 512 + o0 + o] = sg * tanhf(f);
        }
    }
}

// ---------------- launch ----------------
extern "C" void kernel_launch(void* const* d_in, const int* in_sizes, int n_in,
                              void* d_out, int out_size)
{
    const float* q      = (const float*)d_in[0];
    const float* k      = (const float*)d_in[1];
    const float* v      = (const float*)d_in[2];
    const float* Wq     = (const float*)d_in[3];
    const float* Wk     = (const float*)d_in[4];
    const float* Wv     = (const float*)d_in[5];
    const float* fc_w   = (const float*)d_in[6];
    const float* fc_b   = (const float*)d_in[7];
    const float* gate_w = (const float*)d_in[8];
    const float* gate_b = (const float*)d_in[9];
    float* out = (float*)d_out;
    (void)in_sizes; (void)n_in; (void)out_size;

    void *qp_, *kp_, *vp_;
    cudaGetSymbolAddress(&qp_, g_qp);
    cudaGetSymbolAddress(&kp_, g_kp);
    cudaGetSymbolAddress(&vp_, g_vpart);
    float* qp = (float*)qp_;
    float* kp = (float*)kp_;
    float* vpart = (float*)vp_;

    cudaFuncSetAttribute(sgemm_tf32x3,
                         cudaFuncAttributeMaxDynamicSharedMemorySize, SMEM_BYTES);

    // merged q+k grouped projections: z 0..63 -> q, 64..127 -> k
    dim3 gProj(4, 2, 128);
    sgemm_tf32x3<<<gProj, 256, SMEM_BYTES>>>(
        q, Wq, qp, k, Wk, kp,
        32768, 512, 512, 262144, 32768, 512,
        32, 1, 0, 64);

    // vsum: (256 x 32768) @ (32768 x 512), split-K=32 (chunk K=1024)
    dim3 gV(4, 2, VSPLIT);
    sgemm_tf32x3<<<gV, 256, SMEM_BYTES>>>(
        v, Wv, vpart, v, Wv, vpart,
        32768, 0, 512, 0, 512, 0,
        64, VSPLIT, VSUM_ELEMS, VSPLIT);
    reduce_vsum<<<VSUM_ELEMS / 1024, 256>>>();

    attn_kernel<<<dim3(NH, Bb), 256>>>();
    fg_kernel<<<dim3(NH, 8, 4), 256>>>(fc_w, gate_w);
    final_kernel<<<dim3(4, Bb), 256>>>(fc_b, gate_b, out);
}

// round 6
// speedup vs baseline: 15.0902x; 1.5398x over previous
#include <cuda_runtime.h>
#include <cuda_bf16.h>
#include <math.h>
#include <stdint.h>

#define Bb   256
#define NR   64
#define NH   8
#define Ee   512
#define TOPKK 16
#define EPSF 1e-7f

#define VSPLIT 32
#define VSUM_ELEMS (Bb * Ee)

// ---------------- device scratch ----------------
__device__ float g_qp[Bb * NR * Ee];
__device__ float g_kp[Bb * NR * Ee];
__device__ float g_vpart[VSPLIT * VSUM_ELEMS];
__device__ float g_vsum[VSUM_ELEMS];
__device__ float g_attn[Bb * NR * NH];
__device__ float g_F[Bb * NH * Ee];
__device__ float g_G[Bb * NH * Ee];

// ---------------- smem geometry (bytes) ----------------
// A plane: 128 rows x 80B (32 bf16 + pad)   = 10240
// B plane: 32 rows x 272B (128 bf16 + pad)  = 8704
#define APITCH_B 80
#define BPITCH_B 272
#define APL 10240
#define BPL 8704
#define AOFF 0
#define BOFF (2 * APL)                 /* 20480 */
#define BUFSZ (2 * APL + 2 * BPL)      /* 37888 */
#define GEMM_SMEM (2 * BUFSZ)          /* 75776 */

__device__ __forceinline__ uint32_t smem_u32(const void* p) {
    uint32_t a;
    asm("{ .reg .u64 t; cvta.to.shared.u64 t, %1; cvt.u32.u64 %0, t; }" : "=r"(a) : "l"(p));
    return a;
}

__device__ __forceinline__ void ldm_x4(uint32_t* r, uint32_t addr) {
    asm volatile("ldmatrix.sync.aligned.m8n8.x4.shared.b16 {%0,%1,%2,%3}, [%4];"
                 : "=r"(r[0]), "=r"(r[1]), "=r"(r[2]), "=r"(r[3]) : "r"(addr));
}
__device__ __forceinline__ void ldm_x4t(uint32_t* r, uint32_t addr) {
    asm volatile("ldmatrix.sync.aligned.m8n8.x4.trans.shared.b16 {%0,%1,%2,%3}, [%4];"
                 : "=r"(r[0]), "=r"(r[1]), "=r"(r[2]), "=r"(r[3]) : "r"(addr));
}

// split fp32 -> (hi, mid) bf16 pairs, pack 4 lanes into uint2 per plane
__device__ __forceinline__ void split2_pack(float4 v, uint2& hw, uint2& mw) {
    unsigned short h[4], m[4];
    float e[4] = {v.x, v.y, v.z, v.w};
#pragma unroll
    for (int j = 0; j < 4; j++) {
        __nv_bfloat16 hb = __float2bfloat16_rn(e[j]);
        float r1 = e[j] - __bfloat162float(hb);
        __nv_bfloat16 mb = __float2bfloat16_rn(r1);
        h[j] = __bfloat16_as_ushort(hb);
        m[j] = __bfloat16_as_ushort(mb);
    }
    hw.x = (uint32_t)h[0] | ((uint32_t)h[1] << 16);
    hw.y = (uint32_t)h[2] | ((uint32_t)h[3] << 16);
    mw.x = (uint32_t)m[0] | ((uint32_t)m[1] << 16);
    mw.y = (uint32_t)m[2] | ((uint32_t)m[3] << 16);
}

// ---------------- bf16x3 mma.sync GEMM: C = A @ W ----------------
// BM=128 BN=128 BK=32, 256 threads (8 warps 2x4), warp tile 64x32.
// z<32: vsum split-K (K=1024 each); z in [32,96): qproj group; [96,160): kproj.
__global__ __launch_bounds__(256) void gemm_bf16x3(
    const float* __restrict__ q, const float* __restrict__ k,
    const float* __restrict__ v, const float* __restrict__ Wq,
    const float* __restrict__ Wk, const float* __restrict__ Wv)
{
    extern __shared__ char smc[];
    uint32_t sb = smem_u32(smc);
    int tid = threadIdx.x, lane = tid & 31, warp = tid >> 5;
    int z = blockIdx.z;
    long bm = (long)blockIdx.y * 128;
    int n0 = blockIdx.x * 128;

    const float* A; const float* W; float* C;
    long lda, ldc; int nChunks;
    if (z < 32) {
        A = v + (long)z * 1024;
        W = Wv + (long)z * 1024 * 512;
        C = g_vpart + (long)z * VSUM_ELEMS;
        lda = 32768; ldc = 512; nChunks = 32;       /* K = 1024 */
    } else if (z < 96) {
        int g = z - 32;
        A = q + (long)g * 512; W = Wq + (long)g * 262144;
        C = g_qp + (long)g * 512; lda = 32768; ldc = 32768; nChunks = 16;
    } else {
        int g = z - 96;
        A = k + (long)g * 512; W = Wk + (long)g * 262144;
        C = g_kp + (long)g * 512; lda = 32768; ldc = 32768; nChunks = 16;
    }

    int wm0 = (warp >> 2) * 64;
    int wn0 = (warp & 3) * 32;
    int g8 = lane >> 2, tq = lane & 3;

    // ldmatrix per-lane row mapping
    int lrow = ((lane >> 3) & 1) * 8 + (lane & 7);     // row within 16
    int lk16 = ((lane >> 4) & 1) * 16;                  // 8 halves -> 16 bytes
    uint32_t aLane = sb + AOFF + (uint32_t)(wm0 + lrow) * APITCH_B + lk16;
    uint32_t bLane = sb + BOFF + (uint32_t)lrow * BPITCH_B + (uint32_t)(wn0 + ((lane >> 4) & 1) * 8) * 2;

    // global loader mapping
    int am = tid >> 3, akf = (tid & 7) * 4;             // A: 4 iters cover 128 rows
    int bk = tid >> 6, bnf = (tid & 63) * 2;            // B: 4 iters cover 32 rows... (see below)
    // B: 32 rows x 128 cols = 4096 floats; per thread 16 floats = 4 float4
    // lin = tid + i*256: kk = lin>>5 (0..31? 1024 lin /32 = 32), nf = lin&31
    const float* Aload = A + (bm + am) * lda + akf;
    (void)bk; (void)bnf;

    float acc[4][4][4];
#pragma unroll
    for (int mi = 0; mi < 4; mi++)
#pragma unroll
        for (int ni = 0; ni < 4; ni++)
#pragma unroll
            for (int c = 0; c < 4; c++) acc[mi][ni][c] = 0.f;

    float4 ra[4], rb[4];

#define LOADG(kb)                                                              \
    do {                                                                       \
        _Pragma("unroll")                                                      \
        for (int i = 0; i < 4; i++) {                                          \
            ra[i] = *(const float4*)(Aload + (long)(i * 32) * lda + (kb));     \
            int lin = tid + i * 256;                                           \
            int kk = lin >> 5, nf = lin & 31;                                  \
            rb[i] = *(const float4*)(W + ((kb) + kk) * 512 + n0 + nf * 4);     \
        }                                                                      \
    } while (0)

#define STORE(buf)                                                             \
    do {                                                                       \
        char* bp = smc + (buf) * BUFSZ;                                        \
        _Pragma("unroll")                                                      \
        for (int i = 0; i < 4; i++) {                                          \
            uint2 hw, mw;                                                      \
            split2_pack(ra[i], hw, mw);                                        \
            char* ap = bp + AOFF + (am + i * 32) * APITCH_B + akf * 2;         \
            *(uint2*)ap = hw;                                                  \
            *(uint2*)(ap + APL) = mw;                                          \
            split2_pack(rb[i], hw, mw);                                        \
            int lin = tid + i * 256;                                           \
            int kk = lin >> 5, nf = lin & 31;                                  \
            char* wp = bp + BOFF + kk * BPITCH_B + nf * 8;                     \
            *(uint2*)wp = hw;                                                  \
            *(uint2*)(wp + BPL) = mw;                                          \
        }                                                                      \
    } while (0)

#define MMA(AF, BF, mi, ni)                                                    \
    asm volatile(                                                              \
        "mma.sync.aligned.m16n8k16.row.col.f32.bf16.bf16.f32 "                 \
        "{%0,%1,%2,%3}, {%4,%5,%6,%7}, {%8,%9}, {%0,%1,%2,%3};"                \
        : "+f"(acc[mi][ni][0]), "+f"(acc[mi][ni][1]),                          \
          "+f"(acc[mi][ni][2]), "+f"(acc[mi][ni][3])                           \
        : "r"(AF[mi][0]), "r"(AF[mi][1]), "r"(AF[mi][2]), "r"(AF[mi][3]),      \
          "r"(BF[ni][0]), "r"(BF[ni][1]))

    LOADG(0);
    STORE(0);
    if (nChunks > 1) LOADG(32);
    __syncthreads();

    for (int kt = 0; kt < nChunks; kt++) {
        int cur = kt & 1;
        if (kt + 1 < nChunks) {
            STORE(cur ^ 1);
            if (kt + 2 < nChunks) LOADG((long)(kt + 2) * 32);
        }
        uint32_t bufOff = (uint32_t)cur * BUFSZ;
#pragma unroll
        for (int ks = 0; ks < 2; ks++) {
            uint32_t Ah[4][4], Am[4][4];
#pragma unroll
            for (int mt = 0; mt < 4; mt++) {
                uint32_t ad = aLane + bufOff + mt * (16 * APITCH_B) + ks * 32;
                ldm_x4(Ah[mt], ad);
                ldm_x4(Am[mt], ad + APL);
            }
            uint32_t Bh[4][2], Bm[4][2];
#pragma unroll
            for (int pr = 0; pr < 2; pr++) {
                uint32_t bd = bLane + bufOff + ks * (16 * BPITCH_B) + pr * 32;
                uint32_t r4[4];
                ldm_x4t(r4, bd);
                Bh[2 * pr][0] = r4[0]; Bh[2 * pr][1] = r4[1];
                Bh[2 * pr + 1][0] = r4[2]; Bh[2 * pr + 1][1] = r4[3];
                ldm_x4t(r4, bd + BPL);
                Bm[2 * pr][0] = r4[0]; Bm[2 * pr][1] = r4[1];
                Bm[2 * pr + 1][0] = r4[2]; Bm[2 * pr + 1][1] = r4[3];
            }
#pragma unroll
            for (int mt = 0; mt < 4; mt++)
#pragma unroll
                for (int nt = 0; nt < 4; nt++) {
                    MMA(Am, Bh, mt, nt);
                    MMA(Ah, Bm, mt, nt);
                    MMA(Ah, Bh, mt, nt);
                }
        }
        __syncthreads();
    }
#undef MMA
#undef LOADG
#undef STORE

    // epilogue
#pragma unroll
    for (int mt = 0; mt < 4; mt++) {
        long r0 = bm + wm0 + mt * 16 + g8;
#pragma unroll
        for (int nt = 0; nt < 4; nt++) {
            long c0 = n0 + wn0 + nt * 8 + 2 * tq;
            *(float2*)(C + r0 * ldc + c0) = make_float2(acc[mt][nt][0], acc[mt][nt][1]);
            *(float2*)(C + (r0 + 8) * ldc + c0) = make_float2(acc[mt][nt][2], acc[mt][nt][3]);
        }
    }
}

// ---------------- split-K reduction for vsum (float4) ----------------
__global__ __launch_bounds__(256) void reduce_vsum()
{
    int idx = (blockIdx.x * 256 + threadIdx.x) * 4;
    float4 s = make_float4(0.f, 0.f, 0.f, 0.f);
#pragma unroll
    for (int i = 0; i < VSPLIT; i++) {
        float4 p = *(const float4*)&g_vpart[(long)i * VSUM_ELEMS + idx];
        s.x += p.x; s.y += p.y; s.z += p.z; s.w += p.w;
    }
    *(float4*)&g_vsum[idx] = s;
}

// ---------------- attention weights ----------------
__global__ __launch_bounds__(256) void attn_kernel()
{
    __shared__ float Qs[64][65];
    __shared__ float Kst[64][68];
    __shared__ float ev[64], av[64], wv[64];
    __shared__ float red[2], red2[2];
    __shared__ int cntS[4][64];
    __shared__ float dsh;
    int h = blockIdx.x, b = blockIdx.y;
    int t = threadIdx.x;
    int lane = t & 31, wid = t >> 5;

    const float* qpB = g_qp + (long)b * 64 * 512 + h * 64;
    const float* kpB = g_kp + (long)b * 64 * 512 + h * 64;
    for (int i = t; i < 4096; i += 256) {
        int r = i >> 6, k = i & 63;
        Qs[r][k] = qpB[(long)r * 512 + k];
        Kst[k][r] = kpB[(long)r * 512 + k];
    }
    __syncthreads();

    int r0 = (t >> 4) * 4, l0 = (t & 15) * 4;
    float acc[4][4];
#pragma unroll
    for (int i = 0; i < 4; i++)
#pragma unroll
        for (int j = 0; j < 4; j++) acc[i][j] = 0.f;
    for (int k = 0; k < 64; k++) {
        float4 kv = *(const float4*)&Kst[k][l0];
#pragma unroll
        for (int i = 0; i < 4; i++) {
            float qv = Qs[r0 + i][k];
            acc[i][0] = fmaf(qv, kv.x, acc[i][0]);
            acc[i][1] = fmaf(qv, kv.y, acc[i][1]);
            acc[i][2] = fmaf(qv, kv.z, acc[i][2]);
            acc[i][3] = fmaf(qv, kv.w, acc[i][3]);
        }
    }
    float mx[4];
#pragma unroll
    for (int i = 0; i < 4; i++) {
        float m = acc[i][0];
#pragma unroll
        for (int j = 1; j < 4; j++) m = fmaxf(m, acc[i][j]);
        mx[i] = m;
    }
#pragma unroll
    for (int s = 1; s < 16; s <<= 1) {
#pragma unroll
        for (int i = 0; i < 4; i++)
            mx[i] = fmaxf(mx[i], __shfl_xor_sync(0xffffffffu, mx[i], s));
    }
    if ((t & 15) == 0) {
#pragma unroll
        for (int i = 0; i < 4; i++)
            ev[r0 + i] = expf(mx[i] * 0.125f);
    }
    __syncthreads();

    if (t < 64) {
        float m = ev[t];
#pragma unroll
        for (int s = 16; s > 0; s >>= 1) m = fmaxf(m, __shfl_xor_sync(0xffffffffu, m, s));
        if (lane == 0) red[wid] = m;
    }
    __syncthreads();
    if (t < 64) {
        float m = fmaxf(red[0], red[1]);
        float sx = expf(ev[t] - m);
        av[t] = sx;
        float ss = sx;
#pragma unroll
        for (int s = 16; s > 0; s >>= 1) ss += __shfl_xor_sync(0xffffffffu, ss, s);
        if (lane == 0) red2[wid] = ss;
    }
    __syncthreads();
    if (t < 64) av[t] = av[t] / (red2[0] + red2[1]);
    __syncthreads();

    {
        int r = t & 63, part = t >> 6;
        float ar = av[r];
        int cnt = 0;
        int j0 = part * 16;
#pragma unroll
        for (int j = 0; j < 16; j++) {
            float o = av[j0 + j];
            cnt += (o > ar) || (o == ar && (j0 + j) < r);
        }
        cntS[part][r] = cnt;
    }
    __syncthreads();
    if (t < 64) {
        int cnt = cntS[0][t] + cntS[1][t] + cntS[2][t] + cntS[3][t];
        if (cnt == TOPKK - 1) dsh = av[t];
    }
    __syncthreads();
    if (t < 64) {
        float w = fmaxf(av[t] - (dsh + EPSF), 0.f);
        wv[t] = w;
        float ws = w;
#pragma unroll
        for (int s = 16; s > 0; s >>= 1) ws += __shfl_xor_sync(0xffffffffu, ws, s);
        if (lane == 0) red[wid] = ws;
    }
    __syncthreads();
    if (t < 64)
        g_attn[((long)b * 64 + t) * 8 + h] = wv[t] / (red[0] + red[1] + EPSF);
}

// ---------------- F/G factor matrices ----------------
__global__ __launch_bounds__(256) void fg_kernel(const float* __restrict__ fc_w,
                                                 const float* __restrict__ gate_w)
{
    __shared__ float wsm[64][65];
    __shared__ float vssm[64][65];
    int h = blockIdx.x;
    int o0 = blockIdx.y * 64;
    int b0 = blockIdx.z * 64;
    int t = threadIdx.x;

    for (int i = t; i < 64 * 16; i += 256) {
        int bi = i >> 4, d4 = (i & 15) * 4;
        float4 vv = *(const float4*)&g_vsum[((long)(b0 + bi)) * 512 + h * 64 + d4];
        vssm[d4 + 0][bi] = vv.x;
        vssm[d4 + 1][bi] = vv.y;
        vssm[d4 + 2][bi] = vv.z;
        vssm[d4 + 3][bi] = vv.w;
    }
    __syncthreads();

    int bb = (t >> 4) * 4, oo = (t & 15) * 4;
    for (int pass = 0; pass < 2; pass++) {
        const float* Wp = pass ? gate_w : fc_w;
        float* Out = pass ? g_G : g_F;
        for (int i = t; i < 64 * 16; i += 256) {
            int o = i >> 4, d4 = (i & 15) * 4;
            float4 wv4 = *(const float4*)&Wp[((long)(o0 + o)) * 512 + h * 64 + d4];
            wsm[d4 + 0][o] = wv4.x;
            wsm[d4 + 1][o] = wv4.y;
            wsm[d4 + 2][o] = wv4.z;
            wsm[d4 + 3][o] = wv4.w;
        }
        __syncthreads();
        float acc[4][4];
#pragma unroll
        for (int i = 0; i < 4; i++)
#pragma unroll
            for (int j = 0; j < 4; j++) acc[i][j] = 0.f;
        for (int d = 0; d < 64; d++) {
            float vv[4], ww[4];
#pragma unroll
            for (int i = 0; i < 4; i++) vv[i] = vssm[d][bb + i];
#pragma unroll
            for (int j = 0; j < 4; j++) ww[j] = wsm[d][oo + j];
#pragma unroll
            for (int i = 0; i < 4; i++)
#pragma unroll
                for (int j = 0; j < 4; j++)
                    acc[i][j] = fmaf(vv[i], ww[j], acc[i][j]);
        }
#pragma unroll
        for (int i = 0; i < 4; i++)
#pragma unroll
            for (int j = 0; j < 4; j++)
                Out[((long)(b0 + bb + i) * 8 + h) * 512 + o0 + oo + j] = acc[i][j];
        __syncthreads();
    }
}

// ---------------- final gated combine ----------------
__global__ __launch_bounds__(256) void final_kernel(const float* __restrict__ fc_b,
                                                    const float* __restrict__ gate_b,
                                                    float* __restrict__ out)
{
    __shared__ float aw[64][8];
    __shared__ float Fs[8][128];
    __shared__ float Gs[8][128];
    __shared__ float fb[128], gb[128];
    int o0 = blockIdx.x * 128;
    int b = blockIdx.y;
    int t = threadIdx.x;

    for (int i = t; i < 512; i += 256)
        ((float*)aw)[i] = g_attn[(long)b * 512 + i];
    for (int i = t; i < 1024; i += 256) {
        int h = i >> 7, o = i & 127;
        Fs[h][o] = g_F[((long)b * 8 + h) * 512 + o0 + o];
        Gs[h][o] = g_G[((long)b * 8 + h) * 512 + o0 + o];
    }
    if (t < 128) {
        fb[t] = fc_b[o0 + t];
        gb[t] = gate_b[o0 + t];
    }
    __syncthreads();

    int oc = t & 31, rw = t >> 5;
    for (int r = rw; r < 64; r += 8) {
        float ah[8];
#pragma unroll
        for (int h = 0; h < 8; h++) ah[h] = aw[r][h];
        for (int ob = 0; ob < 128; ob += 32) {
            int o = ob + oc;
            float f = fb[o], g = gb[o];
#pragma unroll
            for (int h = 0; h < 8; h++) {
                f = fmaf(ah[h], Fs[h][o], f);
                g = fmaf(ah[h], Gs[h][o], g);
            }
            float sg = 1.f / (1.f + expf(-g));
            out[((long)b * 64 + r) * 512 + o0 + o] = sg * tanhf(f);
        }
    }
}

// ---------------- launch ----------------
extern "C" void kernel_launch(void* const* d_in, const int* in_sizes, int n_in,
                              void* d_out, int out_size)
{
    const float* q      = (const float*)d_in[0];
    const float* k      = (const float*)d_in[1];
    const float* v      = (const float*)d_in[2];
    const float* Wq     = (const float*)d_in[3];
    const float* Wk     = (const float*)d_in[4];
    const float* Wv     = (const float*)d_in[5];
    const float* fc_w   = (const float*)d_in[6];
    const float* fc_b   = (const float*)d_in[7];
    const float* gate_w = (const float*)d_in[8];
    const float* gate_b = (const float*)d_in[9];
    float* out = (float*)d_out;
    (void)in_sizes; (void)n_in; (void)out_size;

    cudaFuncSetAttribute(gemm_bf16x3, cudaFuncAttributeMaxDynamicSharedMemorySize,
                         GEMM_SMEM);

    // fused bf16x3 GEMMs: z<32 vsum split-K (K=1024 each), z<96 qproj, else kproj
    gemm_bf16x3<<<dim3(4, 2, 160), 256, GEMM_SMEM>>>(q, k, v, Wq, Wk, Wv);
    reduce_vsum<<<VSUM_ELEMS / 1024, 256>>>();

    attn_kernel<<<dim3(NH, Bb), 256>>>();
    fg_kernel<<<dim3(NH, 8, 4), 256>>>(fc_w, gate_w);
    final_kernel<<<dim3(4, Bb), 256>>>(fc_b, gate_b, out);
}

// round 8
// speedup vs baseline: 17.2264x; 1.1416x over previous
#include <cuda_runtime.h>
#include <cuda_bf16.h>
#include <cuda_fp16.h>
#include <math.h>
#include <stdint.h>

#define Bb   256
#define NR   64
#define NH   8
#define Ee   512
#define TOPKK 16
#define EPSF 1e-7f

#define VSPLIT 32
#define VSUM_ELEMS (Bb * Ee)

// ---------------- device scratch ----------------
__device__ float g_qp[Bb * NR * Ee];
__device__ float g_kp[Bb * NR * Ee];
__device__ float g_vpart[VSPLIT * VSUM_ELEMS];
__device__ float g_vsum[VSUM_ELEMS];
__device__ float g_attn[Bb * NR * NH];
__device__ float g_F[Bb * NH * Ee];
__device__ float g_G[Bb * NH * Ee];

// ---------------- smem geometry for GEMM (bytes) ----------------
#define APITCH_B 80
#define BPITCH_B 272
#define APL 10240
#define BPL 8704
#define AOFF 0
#define BOFF (2 * APL)
#define BUFSZ (2 * APL + 2 * BPL)      /* 37888 */
#define GEMM_SMEM (2 * BUFSZ)          /* 75776 */

__device__ __forceinline__ uint32_t smem_u32(const void* p) {
    uint32_t a;
    asm("{ .reg .u64 t; cvta.to.shared.u64 t, %1; cvt.u32.u64 %0, t; }" : "=r"(a) : "l"(p));
    return a;
}
__device__ __forceinline__ void ldm_x4(uint32_t* r, uint32_t addr) {
    asm volatile("ldmatrix.sync.aligned.m8n8.x4.shared.b16 {%0,%1,%2,%3}, [%4];"
                 : "=r"(r[0]), "=r"(r[1]), "=r"(r[2]), "=r"(r[3]) : "r"(addr));
}
__device__ __forceinline__ void ldm_x4t(uint32_t* r, uint32_t addr) {
    asm volatile("ldmatrix.sync.aligned.m8n8.x4.trans.shared.b16 {%0,%1,%2,%3}, [%4];"
                 : "=r"(r[0]), "=r"(r[1]), "=r"(r[2]), "=r"(r[3]) : "r"(addr));
}

// fp32 -> (hi, mid) bf16 planes packed as uint2 (4 lanes)
__device__ __forceinline__ void split2_pack(float4 v, uint2& hw, uint2& mw) {
    unsigned short h[4], m[4];
    float e[4] = {v.x, v.y, v.z, v.w};
#pragma unroll
    for (int j = 0; j < 4; j++) {
        __nv_bfloat16 hb = __float2bfloat16_rn(e[j]);
        float r1 = e[j] - __bfloat162float(hb);
        __nv_bfloat16 mb = __float2bfloat16_rn(r1);
        h[j] = __bfloat16_as_ushort(hb);
        m[j] = __bfloat16_as_ushort(mb);
    }
    hw.x = (uint32_t)h[0] | ((uint32_t)h[1] << 16);
    hw.y = (uint32_t)h[2] | ((uint32_t)h[3] << 16);
    mw.x = (uint32_t)m[0] | ((uint32_t)m[1] << 16);
    mw.y = (uint32_t)m[2] | ((uint32_t)m[3] << 16);
}
// fp32 -> f16 single plane
__device__ __forceinline__ uint2 f16_pack(float4 v) {
    unsigned short h[4];
    float e[4] = {v.x, v.y, v.z, v.w};
#pragma unroll
    for (int j = 0; j < 4; j++) h[j] = __half_as_ushort(__float2half_rn(e[j]));
    uint2 w;
    w.x = (uint32_t)h[0] | ((uint32_t)h[1] << 16);
    w.y = (uint32_t)h[2] | ((uint32_t)h[3] << 16);
    return w;
}

#define MMA_BF(AF, BF, mi, ni)                                                 \
    asm volatile(                                                              \
        "mma.sync.aligned.m16n8k16.row.col.f32.bf16.bf16.f32 "                 \
        "{%0,%1,%2,%3}, {%4,%5,%6,%7}, {%8,%9}, {%0,%1,%2,%3};"                \
        : "+f"(acc[mi][ni][0]), "+f"(acc[mi][ni][1]),                          \
          "+f"(acc[mi][ni][2]), "+f"(acc[mi][ni][3])                           \
        : "r"(AF[mi][0]), "r"(AF[mi][1]), "r"(AF[mi][2]), "r"(AF[mi][3]),      \
          "r"(BF[ni][0]), "r"(BF[ni][1]))
#define MMA_F16(AF, BF, mi, ni)                                                \
    asm volatile(                                                              \
        "mma.sync.aligned.m16n8k16.row.col.f32.f16.f16.f32 "                   \
        "{%0,%1,%2,%3}, {%4,%5,%6,%7}, {%8,%9}, {%0,%1,%2,%3};"                \
        : "+f"(acc[mi][ni][0]), "+f"(acc[mi][ni][1]),                          \
          "+f"(acc[mi][ni][2]), "+f"(acc[mi][ni][3])                           \
        : "r"(AF[mi][0]), "r"(AF[mi][1]), "r"(AF[mi][2]), "r"(AF[mi][3]),      \
          "r"(BF[ni][0]), "r"(BF[ni][1]))

// ---------------- mixed-precision mma.sync GEMM: C = A @ W ----------------
// BM=128 BN=128 BK=32, 256 threads (8 warps 2x4), warp tile 64x32.
// z<64: qproj (bf16x3); z<128: kproj (bf16x3); z>=128: vsum split-K (f16x1).
__global__ __launch_bounds__(256) void gemm_mma(
    const float* __restrict__ q, const float* __restrict__ k,
    const float* __restrict__ v, const float* __restrict__ Wq,
    const float* __restrict__ Wk, const float* __restrict__ Wv)
{
    extern __shared__ char smc[];
    uint32_t sb = smem_u32(smc);
    int tid = threadIdx.x, lane = tid & 31, warp = tid >> 5;
    int z = blockIdx.z;
    long bm = (long)blockIdx.y * 128;
    int n0 = blockIdx.x * 128;

    const float* A; const float* W; float* C;
    long lda, ldc; int nChunks; bool np3;
    if (z < 64) {
        A = q + (long)z * 512; W = Wq + (long)z * 262144;
        C = g_qp + (long)z * 512; lda = 32768; ldc = 32768; nChunks = 16; np3 = true;
    } else if (z < 128) {
        int g = z - 64;
        A = k + (long)g * 512; W = Wk + (long)g * 262144;
        C = g_kp + (long)g * 512; lda = 32768; ldc = 32768; nChunks = 16; np3 = true;
    } else {
        int kz = z - 128;
        A = v + (long)kz * 1024;
        W = Wv + (long)kz * 1024 * 512;
        C = g_vpart + (long)kz * VSUM_ELEMS;
        lda = 32768; ldc = 512; nChunks = 32; np3 = false;
    }

    int wm0 = (warp >> 2) * 64;
    int wn0 = (warp & 3) * 32;
    int g8 = lane >> 2, tq = lane & 3;

    int lrow = ((lane >> 3) & 1) * 8 + (lane & 7);
    int lk16 = ((lane >> 4) & 1) * 16;
    uint32_t aLane = sb + AOFF + (uint32_t)(wm0 + lrow) * APITCH_B + lk16;
    uint32_t bLane = sb + BOFF + (uint32_t)lrow * BPITCH_B + (uint32_t)(wn0 + ((lane >> 4) & 1) * 8) * 2;

    int am = tid >> 3, akf = (tid & 7) * 4;
    const float* Aload = A + (bm + am) * lda + akf;

    float acc[4][4][4];
#pragma unroll
    for (int mi = 0; mi < 4; mi++)
#pragma unroll
        for (int ni = 0; ni < 4; ni++)
#pragma unroll
            for (int c = 0; c < 4; c++) acc[mi][ni][c] = 0.f;

    float4 ra[4], rb[4];

#define LOADG(kb)                                                              \
    do {                                                                       \
        _Pragma("unroll")                                                      \
        for (int i = 0; i < 4; i++) {                                          \
            ra[i] = *(const float4*)(Aload + (long)(i * 32) * lda + (kb));     \
            int lin = tid + i * 256;                                           \
            int kk = lin >> 5, nf = lin & 31;                                  \
            rb[i] = *(const float4*)(W + ((kb) + kk) * 512 + n0 + nf * 4);     \
        }                                                                      \
    } while (0)

#define STORE(buf)                                                             \
    do {                                                                       \
        char* bp = smc + (buf) * BUFSZ;                                        \
        _Pragma("unroll")                                                      \
        for (int i = 0; i < 4; i++) {                                          \
            char* ap = bp + AOFF + (am + i * 32) * APITCH_B + akf * 2;         \
            int lin = tid + i * 256;                                           \
            int kk = lin >> 5, nf = lin & 31;                                  \
            char* wp = bp + BOFF + kk * BPITCH_B + nf * 8;                     \
            if (np3) {                                                         \
                uint2 hw, mw;                                                  \
                split2_pack(ra[i], hw, mw);                                    \
                *(uint2*)ap = hw; *(uint2*)(ap + APL) = mw;                    \
                split2_pack(rb[i], hw, mw);                                    \
                *(uint2*)wp = hw; *(uint2*)(wp + BPL) = mw;                    \
            } else {                                                           \
                *(uint2*)ap = f16_pack(ra[i]);                                 \
                *(uint2*)wp = f16_pack(rb[i]);                                 \
            }                                                                  \
        }                                                                      \
    } while (0)

    LOADG(0);
    STORE(0);
    if (nChunks > 1) LOADG(32);
    __syncthreads();

    for (int kt = 0; kt < nChunks; kt++) {
        int cur = kt & 1;
        if (kt + 1 < nChunks) {
            STORE(cur ^ 1);
            if (kt + 2 < nChunks) LOADG((long)(kt + 2) * 32);
        }
        uint32_t bufOff = (uint32_t)cur * BUFSZ;
#pragma unroll
        for (int ks = 0; ks < 2; ks++) {
            uint32_t Ah[4][4], Am[4][4];
#pragma unroll
            for (int mt = 0; mt < 4; mt++) {
                uint32_t ad = aLane + bufOff + mt * (16 * APITCH_B) + ks * 32;
                ldm_x4(Ah[mt], ad);
                if (np3) ldm_x4(Am[mt], ad + APL);
            }
            uint32_t Bh[4][2], Bm[4][2];
#pragma unroll
            for (int pr = 0; pr < 2; pr++) {
                uint32_t bd = bLane + bufOff + ks * (16 * BPITCH_B) + pr * 32;
                uint32_t r4[4];
                ldm_x4t(r4, bd);
                Bh[2 * pr][0] = r4[0]; Bh[2 * pr][1] = r4[1];
                Bh[2 * pr + 1][0] = r4[2]; Bh[2 * pr + 1][1] = r4[3];
                if (np3) {
                    ldm_x4t(r4, bd + BPL);
                    Bm[2 * pr][0] = r4[0]; Bm[2 * pr][1] = r4[1];
                    Bm[2 * pr + 1][0] = r4[2]; Bm[2 * pr + 1][1] = r4[3];
                }
            }
            if (np3) {
#pragma unroll
                for (int mt = 0; mt < 4; mt++)
#pragma unroll
                    for (int nt = 0; nt < 4; nt++) {
                        MMA_BF(Am, Bh, mt, nt);
                        MMA_BF(Ah, Bm, mt, nt);
                        MMA_BF(Ah, Bh, mt, nt);
                    }
            } else {
#pragma unroll
                for (int mt = 0; mt < 4; mt++)
#pragma unroll
                    for (int nt = 0; nt < 4; nt++)
                        MMA_F16(Ah, Bh, mt, nt);
            }
        }
        __syncthreads();
    }
#undef LOADG
#undef STORE

#pragma unroll
    for (int mt = 0; mt < 4; mt++) {
        long r0 = bm + wm0 + mt * 16 + g8;
#pragma unroll
        for (int nt = 0; nt < 4; nt++) {
            long c0 = n0 + wn0 + nt * 8 + 2 * tq;
            *(float2*)(C + r0 * ldc + c0) = make_float2(acc[mt][nt][0], acc[mt][nt][1]);
            *(float2*)(C + (r0 + 8) * ldc + c0) = make_float2(acc[mt][nt][2], acc[mt][nt][3]);
        }
    }
}

// ---------------- split-K reduction for vsum ----------------
__global__ __launch_bounds__(256) void reduce_vsum()
{
    int idx = (blockIdx.x * 256 + threadIdx.x) * 4;
    float4 s = make_float4(0.f, 0.f, 0.f, 0.f);
#pragma unroll
    for (int i = 0; i < VSPLIT; i++) {
        float4 p = *(const float4*)&g_vpart[(long)i * VSUM_ELEMS + idx];
        s.x += p.x; s.y += p.y; s.z += p.z; s.w += p.w;
    }
    *(float4*)&g_vsum[idx] = s;
}

// ---------------- attention weights (MMA-based scores) ----------------
__global__ __launch_bounds__(256) void attn_kernel()
{
    __shared__ __align__(16) unsigned short Qh[64 * 72], Qm[64 * 72];
    __shared__ __align__(16) unsigned short Kh[64 * 72], Km[64 * 72];
    __shared__ float colmax[2][64];
    __shared__ float ev[64], av[64], wv[64];
    __shared__ float red[2], red2[2];
    __shared__ int cntS[4][64];
    __shared__ float dsh;
    int h = blockIdx.x, b = blockIdx.y;
    int t = threadIdx.x, lane = t & 31, w = t >> 5;

    const float* qpB = g_qp + (long)b * 64 * 512 + h * 64;
    const float* kpB = g_kp + (long)b * 64 * 512 + h * 64;
#pragma unroll
    for (int i = 0; i < 4; i++) {
        int idx = t + i * 256;
        int r = idx >> 4, c4 = (idx & 15) * 4;
        float4 qv = *(const float4*)(qpB + (long)r * 512 + c4);
        float4 kv = *(const float4*)(kpB + (long)r * 512 + c4);
        uint2 hw, mw;
        split2_pack(qv, hw, mw);
        *(uint2*)&Qh[r * 72 + c4] = hw;
        *(uint2*)&Qm[r * 72 + c4] = mw;
        split2_pack(kv, hw, mw);
        *(uint2*)&Kh[r * 72 + c4] = hw;
        *(uint2*)&Km[r * 72 + c4] = mw;
    }
    __syncthreads();

    int wr = w & 3, wc = w >> 2;
    int r0 = wr * 16, n0 = wc * 32;
    int am_row = r0 + ((lane >> 3) & 1) * 8 + (lane & 7);
    int am_col = (lane >> 4) * 16;
    uint32_t aQh = smem_u32(Qh) + am_row * 144 + am_col;
    uint32_t aQm = smem_u32(Qm) + am_row * 144 + am_col;
    int sel = (lane >> 3) & 3;
    int brow = (sel >> 1) * 8 + (lane & 7);
    int bcol = (sel & 1) * 16;
    uint32_t aKh = smem_u32(Kh) + bcol;
    uint32_t aKm = smem_u32(Km) + bcol;

    float acc[4][4];
#pragma unroll
    for (int i = 0; i < 4; i++)
#pragma unroll
        for (int j = 0; j < 4; j++) acc[i][j] = 0.f;

#pragma unroll
    for (int ks = 0; ks < 4; ks++) {
        uint32_t Ah[4], Am[4];
        ldm_x4(Ah, aQh + ks * 32);
        ldm_x4(Am, aQm + ks * 32);
#pragma unroll
        for (int ntp = 0; ntp < 2; ntp++) {
            uint32_t off = (uint32_t)(n0 + ntp * 16 + brow) * 144 + ks * 32;
            uint32_t r4[4];
            uint32_t Bh[2][2], Bm[2][2];
            ldm_x4(r4, aKh + off);
            Bh[0][0] = r4[0]; Bh[0][1] = r4[1]; Bh[1][0] = r4[2]; Bh[1][1] = r4[3];
            ldm_x4(r4, aKm + off);
            Bm[0][0] = r4[0]; Bm[0][1] = r4[1]; Bm[1][0] = r4[2]; Bm[1][1] = r4[3];
#pragma unroll
            for (int j = 0; j < 2; j++) {
                int nt = ntp * 2 + j;
                asm volatile(
                    "mma.sync.aligned.m16n8k16.row.col.f32.bf16.bf16.f32 "
                    "{%0,%1,%2,%3}, {%4,%5,%6,%7}, {%8,%9}, {%0,%1,%2,%3};"
                    : "+f"(acc[nt][0]), "+f"(acc[nt][1]), "+f"(acc[nt][2]), "+f"(acc[nt][3])
                    : "r"(Am[0]), "r"(Am[1]), "r"(Am[2]), "r"(Am[3]),
                      "r"(Bh[j][0]), "r"(Bh[j][1]));
                asm volatile(
                    "mma.sync.aligned.m16n8k16.row.col.f32.bf16.bf16.f32 "
                    "{%0,%1,%2,%3}, {%4,%5,%6,%7}, {%8,%9}, {%0,%1,%2,%3};"
                    : "+f"(acc[nt][0]), "+f"(acc[nt][1]), "+f"(acc[nt][2]), "+f"(acc[nt][3])
                    : "r"(Ah[0]), "r"(Ah[1]), "r"(Ah[2]), "r"(Ah[3]),
                      "r"(Bm[j][0]), "r"(Bm[j][1]));
                asm volatile(
                    "mma.sync.aligned.m16n8k16.row.col.f32.bf16.bf16.f32 "
                    "{%0,%1,%2,%3}, {%4,%5,%6,%7}, {%8,%9}, {%0,%1,%2,%3};"
                    : "+f"(acc[nt][0]), "+f"(acc[nt][1]), "+f"(acc[nt][2]), "+f"(acc[nt][3])
                    : "r"(Ah[0]), "r"(Ah[1]), "r"(Ah[2]), "r"(Ah[3]),
                      "r"(Bh[j][0]), "r"(Bh[j][1]));
            }
        }
    }

    // per-thread row maxes: rows r0 + (lane>>2) and +8
    float m1 = acc[0][0], m2 = acc[0][2];
#pragma unroll
    for (int nt = 0; nt < 4; nt++) {
        m1 = fmaxf(m1, fmaxf(acc[nt][0], acc[nt][1]));
        m2 = fmaxf(m2, fmaxf(acc[nt][2], acc[nt][3]));
    }
    m1 = fmaxf(m1, __shfl_xor_sync(0xffffffffu, m1, 1));
    m1 = fmaxf(m1, __shfl_xor_sync(0xffffffffu, m1, 2));
    m2 = fmaxf(m2, __shfl_xor_sync(0xffffffffu, m2, 1));
    m2 = fmaxf(m2, __shfl_xor_sync(0xffffffffu, m2, 2));
    if ((lane & 3) == 0) {
        colmax[wc][r0 + (lane >> 2)] = m1;
        colmax[wc][r0 + (lane >> 2) + 8] = m2;
    }
    __syncthreads();
    if (t < 64) ev[t] = expf(fmaxf(colmax[0][t], colmax[1][t]) * 0.125f);
    __syncthreads();

    if (t < 64) {
        float m = ev[t];
#pragma unroll
        for (int s = 16; s > 0; s >>= 1) m = fmaxf(m, __shfl_xor_sync(0xffffffffu, m, s));
        if (lane == 0) red[w] = m;
    }
    __syncthreads();
    if (t < 64) {
        float m = fmaxf(red[0], red[1]);
        float sx = expf(ev[t] - m);
        av[t] = sx;
        float ss = sx;
#pragma unroll
        for (int s = 16; s > 0; s >>= 1) ss += __shfl_xor_sync(0xffffffffu, ss, s);
        if (lane == 0) red2[w] = ss;
    }
    __syncthreads();
    if (t < 64) av[t] = av[t] / (red2[0] + red2[1]);
    __syncthreads();

    {
        int r = t & 63, part = t >> 6;
        float ar = av[r];
        int cnt = 0;
        int j0 = part * 16;
#pragma unroll
        for (int j = 0; j < 16; j++) {
            float o = av[j0 + j];
            cnt += (o > ar) || (o == ar && (j0 + j) < r);
        }
        cntS[part][r] = cnt;
    }
    __syncthreads();
    if (t < 64) {
        int cnt = cntS[0][t] + cntS[1][t] + cntS[2][t] + cntS[3][t];
        if (cnt == TOPKK - 1) dsh = av[t];
    }
    __syncthreads();
    if (t < 64) {
        float wq = fmaxf(av[t] - (dsh + EPSF), 0.f);
        wv[t] = wq;
        float ws = wq;
#pragma unroll
        for (int s = 16; s > 0; s >>= 1) ws += __shfl_xor_sync(0xffffffffu, ws, s);
        if (lane == 0) red[w] = ws;
    }
    __syncthreads();
    if (t < 64)
        g_attn[((long)b * 64 + t) * 8 + h] = wv[t] / (red[0] + red[1] + EPSF);
}

// ---------------- fused F/G factor matrices ----------------
// grid (NH, 8 o-tiles of 64, 8 b-tiles of 32), 256 threads
__global__ __launch_bounds__(256) void fg_kernel(const float* __restrict__ fc_w,
                                                 const float* __restrict__ gate_w)
{
    __shared__ float vssm[64][33];
    __shared__ float wf[64][68];   // pitch 68 floats = 272B -> float4-aligned rows
    __shared__ float wg[64][68];
    int h = blockIdx.x;
    int o0 = blockIdx.y * 64;
    int b0 = blockIdx.z * 32;
    int t = threadIdx.x;

#pragma unroll
    for (int i = 0; i < 2; i++) {
        int idx = t + i * 256;
        int bi = idx >> 4, d4 = (idx & 15) * 4;
        float4 vv = *(const float4*)&g_vsum[((long)(b0 + bi)) * 512 + h * 64 + d4];
        vssm[d4 + 0][bi] = vv.x;
        vssm[d4 + 1][bi] = vv.y;
        vssm[d4 + 2][bi] = vv.z;
        vssm[d4 + 3][bi] = vv.w;
    }
#pragma unroll
    for (int i = 0; i < 4; i++) {
        int idx = t + i * 256;
        int o = idx >> 4, d4 = (idx & 15) * 4;
        float4 f4 = *(const float4*)&fc_w[((long)(o0 + o)) * 512 + h * 64 + d4];
        float4 g4 = *(const float4*)&gate_w[((long)(o0 + o)) * 512 + h * 64 + d4];
        wf[d4 + 0][o] = f4.x; wf[d4 + 1][o] = f4.y; wf[d4 + 2][o] = f4.z; wf[d4 + 3][o] = f4.w;
        wg[d4 + 0][o] = g4.x; wg[d4 + 1][o] = g4.y; wg[d4 + 2][o] = g4.z; wg[d4 + 3][o] = g4.w;
    }
    __syncthreads();

    int bb = (t >> 4) * 2, oo = (t & 15) * 4;
    float af[2][4], ag[2][4];
#pragma unroll
    for (int i = 0; i < 2; i++)
#pragma unroll
        for (int j = 0; j < 4; j++) { af[i][j] = 0.f; ag[i][j] = 0.f; }
    for (int d = 0; d < 64; d++) {
        float v0 = vssm[d][bb], v1 = vssm[d][bb + 1];
        float4 f4 = *(const float4*)&wf[d][oo];
        float4 g4 = *(const float4*)&wg[d][oo];
        af[0][0] = fmaf(v0, f4.x, af[0][0]); af[0][1] = fmaf(v0, f4.y, af[0][1]);
        af[0][2] = fmaf(v0, f4.z, af[0][2]); af[0][3] = fmaf(v0, f4.w, af[0][3]);
        af[1][0] = fmaf(v1, f4.x, af[1][0]); af[1][1] = fmaf(v1, f4.y, af[1][1]);
        af[1][2] = fmaf(v1, f4.z, af[1][2]); af[1][3] = fmaf(v1, f4.w, af[1][3]);
        ag[0][0] = fmaf(v0, g4.x, ag[0][0]); ag[0][1] = fmaf(v0, g4.y, ag[0][1]);
        ag[0][2] = fmaf(v0, g4.z, ag[0][2]); ag[0][3] = fmaf(v0, g4.w, ag[0][3]);
        ag[1][0] = fmaf(v1, g4.x, ag[1][0]); ag[1][1] = fmaf(v1, g4.y, ag[1][1]);
        ag[1][2] = fmaf(v1, g4.z, ag[1][2]); ag[1][3] = fmaf(v1, g4.w, ag[1][3]);
    }
#pragma unroll
    for (int i = 0; i < 2; i++) {
        long base = ((long)(b0 + bb + i) * 8 + h) * 512 + o0 + oo;
        *(float4*)&g_F[base] = make_float4(af[i][0], af[i][1], af[i][2], af[i][3]);
        *(float4*)&g_G[base] = make_float4(ag[i][0], ag[i][1], ag[i][2], ag[i][3]);
    }
}

// ---------------- final gated combine ----------------
__global__ __launch_bounds__(256) void final_kernel(const float* __restrict__ fc_b,
                                                    const float* __restrict__ gate_b,
                                                    float* __restrict__ out)
{
    __shared__ float aw[64][8];
    __shared__ float Fs[8][128];
    __shared__ float Gs[8][128];
    __shared__ float fb[128], gb[128];
    int o0 = blockIdx.x * 128;
    int b = blockIdx.y;
    int t = threadIdx.x;

    for (int i = t; i < 512; i += 256)
        ((float*)aw)[i] = g_attn[(long)b * 512 + i];
    for (int i = t; i < 1024; i += 256) {
        int h = i >> 7, o = i & 127;
        Fs[h][o] = g_F[((long)b * 8 + h) * 512 + o0 + o];
        Gs[h][o] = g_G[((long)b * 8 + h) * 512 + o0 + o];
    }
    if (t < 128) {
        fb[t] = fc_b[o0 + t];
        gb[t] = gate_b[o0 + t];
    }
    __syncthreads();

    int oc = t & 31, rw = t >> 5;
    for (int r = rw; r < 64; r += 8) {
        float ah[8];
#pragma unroll
        for (int h = 0; h < 8; h++) ah[h] = aw[r][h];
        for (int ob = 0; ob < 128; ob += 32) {
            int o = ob + oc;
            float f = fb[o], g = gb[o];
#pragma unroll
            for (int h = 0; h < 8; h++) {
                f = fmaf(ah[h], Fs[h][o], f);
                g = fmaf(ah[h], Gs[h][o], g);
            }
            float sg = 1.f / (1.f + expf(-g));
            out[((long)b * 64 + r) * 512 + o0 + o] = sg * tanhf(f);
        }
    }
}

// ---------------- launch ----------------
extern "C" void kernel_launch(void* const* d_in, const int* in_sizes, int n_in,
                              void* d_out, int out_size)
{
    const float* q      = (const float*)d_in[0];
    const float* k      = (const float*)d_in[1];
    const float* v      = (const float*)d_in[2];
    const float* Wq     = (const float*)d_in[3];
    const float* Wk     = (const float*)d_in[4];
    const float* Wv     = (const float*)d_in[5];
    const float* fc_w   = (const float*)d_in[6];
    const float* fc_b   = (const float*)d_in[7];
    const float* gate_w = (const float*)d_in[8];
    const float* gate_b = (const float*)d_in[9];
    float* out = (float*)d_out;
    (void)in_sizes; (void)n_in; (void)out_size;

    cudaFuncSetAttribute(gemm_mma, cudaFuncAttributeMaxDynamicSharedMemorySize,
                         GEMM_SMEM);

    // z<64 qproj (bf16x3), z<128 kproj (bf16x3), z>=128 vsum split-K (f16x1)
    gemm_mma<<<dim3(4, 2, 160), 256, GEMM_SMEM>>>(q, k, v, Wq, Wk, Wv);
    reduce_vsum<<<VSUM_ELEMS / 1024, 256>>>();

    attn_kernel<<<dim3(NH, Bb), 256>>>();
    fg_kernel<<<dim3(NH, 8, 8), 256>>>(fc_w, gate_w);
    final_kernel<<<dim3(4, Bb), 256>>>(fc_b, gate_b, out);
}

// round 10
// speedup vs baseline: 21.2899x; 1.2359x over previous
#include <cuda_runtime.h>
#include <cuda_bf16.h>
#include <cuda_fp16.h>
#include <math.h>
#include <stdint.h>

#define Bb   256
#define NR   64
#define NH   8
#define Ee   512
#define TOPKK 16
#define EPSF 1e-7f

#define VSPLIT 32
#define VSUM_ELEMS (Bb * Ee)

// ---------------- device scratch ----------------
__device__ float g_qp[Bb * NR * Ee];
__device__ float g_kp[Bb * NR * Ee];
__device__ float g_vpart[VSPLIT * VSUM_ELEMS];
__device__ float g_vsum[VSUM_ELEMS];
__device__ float g_attn[Bb * NR * NH];
__device__ float g_F[Bb * NH * Ee];
__device__ float g_G[Bb * NH * Ee];

// ---------------- smem geometry for GEMM (bytes) ----------------
#define APITCH_B 80
#define BPITCH_B 272
#define APL 10240
#define BPL 8704
#define AOFF 0
#define BOFF (2 * APL)
#define BUFSZ (2 * APL + 2 * BPL)      /* 37888 */
#define GEMM_SMEM (2 * BUFSZ)          /* 75776 */

__device__ __forceinline__ uint32_t smem_u32(const void* p) {
    uint32_t a;
    asm("{ .reg .u64 t; cvta.to.shared.u64 t, %1; cvt.u32.u64 %0, t; }" : "=r"(a) : "l"(p));
    return a;
}
__device__ __forceinline__ void ldm_x4(uint32_t* r, uint32_t addr) {
    asm volatile("ldmatrix.sync.aligned.m8n8.x4.shared.b16 {%0,%1,%2,%3}, [%4];"
                 : "=r"(r[0]), "=r"(r[1]), "=r"(r[2]), "=r"(r[3]) : "r"(addr));
}
__device__ __forceinline__ void ldm_x4t(uint32_t* r, uint32_t addr) {
    asm volatile("ldmatrix.sync.aligned.m8n8.x4.trans.shared.b16 {%0,%1,%2,%3}, [%4];"
                 : "=r"(r[0]), "=r"(r[1]), "=r"(r[2]), "=r"(r[3]) : "r"(addr));
}

// packed converts: first src operand -> UPPER half (PTX cvt two-operand form)
__device__ __forceinline__ uint32_t bf2(float up, float lo) {
    uint32_t r;
    asm("cvt.rn.bf16x2.f32 %0, %1, %2;" : "=r"(r) : "f"(up), "f"(lo));
    return r;
}
__device__ __forceinline__ uint32_t hf2(float up, float lo) {
    uint32_t r;
    asm("cvt.rn.f16x2.f32 %0, %1, %2;" : "=r"(r) : "f"(up), "f"(lo));
    return r;
}

// fp32 -> (hi, mid) bf16 planes packed as uint2 (4 lanes), packed-cvt version
__device__ __forceinline__ void split2_pack(float4 v, uint2& hw, uint2& mw) {
    hw.x = bf2(v.y, v.x);
    hw.y = bf2(v.w, v.z);
    float h0 = __uint_as_float(hw.x << 16);
    float h1 = __uint_as_float(hw.x & 0xFFFF0000u);
    float h2 = __uint_as_float(hw.y << 16);
    float h3 = __uint_as_float(hw.y & 0xFFFF0000u);
    mw.x = bf2(v.y - h1, v.x - h0);
    mw.y = bf2(v.w - h3, v.z - h2);
}
// fp32 -> f16 single plane
__device__ __forceinline__ uint2 f16_pack(float4 v) {
    uint2 w;
    w.x = hf2(v.y, v.x);
    w.y = hf2(v.w, v.z);
    return w;
}

#define MMA_BF(AF, BF, mi, ni)                                                 \
    asm volatile(                                                              \
        "mma.sync.aligned.m16n8k16.row.col.f32.bf16.bf16.f32 "                 \
        "{%0,%1,%2,%3}, {%4,%5,%6,%7}, {%8,%9}, {%0,%1,%2,%3};"                \
        : "+f"(acc[mi][ni][0]), "+f"(acc[mi][ni][1]),                          \
          "+f"(acc[mi][ni][2]), "+f"(acc[mi][ni][3])                           \
        : "r"(AF[mi][0]), "r"(AF[mi][1]), "r"(AF[mi][2]), "r"(AF[mi][3]),      \
          "r"(BF[ni][0]), "r"(BF[ni][1]))
#define MMA_F16(AF, BF, mi, ni)                                                \
    asm volatile(                                                              \
        "mma.sync.aligned.m16n8k16.row.col.f32.f16.f16.f32 "                   \
        "{%0,%1,%2,%3}, {%4,%5,%6,%7}, {%8,%9}, {%0,%1,%2,%3};"                \
        : "+f"(acc[mi][ni][0]), "+f"(acc[mi][ni][1]),                          \
          "+f"(acc[mi][ni][2]), "+f"(acc[mi][ni][3])                           \
        : "r"(AF[mi][0]), "r"(AF[mi][1]), "r"(AF[mi][2]), "r"(AF[mi][3]),      \
          "r"(BF[ni][0]), "r"(BF[ni][1]))

// ---------------- mixed-precision mma.sync GEMM: C = A @ W ----------------
// BM=128 BN=128 BK=32, 256 threads (8 warps 2x4), warp tile 64x32.
// z<64: qproj (bf16x3); z<128: kproj (bf16x3); z>=128: vsum split-K (f16x1).
__global__ __launch_bounds__(256) void gemm_mma(
    const float* __restrict__ q, const float* __restrict__ k,
    const float* __restrict__ v, const float* __restrict__ Wq,
    const float* __restrict__ Wk, const float* __restrict__ Wv)
{
    extern __shared__ char smc[];
    uint32_t sb = smem_u32(smc);
    int tid = threadIdx.x, lane = tid & 31, warp = tid >> 5;
    int z = blockIdx.z;
    long bm = (long)blockIdx.y * 128;
    int n0 = blockIdx.x * 128;

    const float* A; const float* W; float* C;
    long lda, ldc; int nChunks; bool np3;
    if (z < 64) {
        A = q + (long)z * 512; W = Wq + (long)z * 262144;
        C = g_qp + (long)z * 512; lda = 32768; ldc = 32768; nChunks = 16; np3 = true;
    } else if (z < 128) {
        int g = z - 64;
        A = k + (long)g * 512; W = Wk + (long)g * 262144;
        C = g_kp + (long)g * 512; lda = 32768; ldc = 32768; nChunks = 16; np3 = true;
    } else {
        int kz = z - 128;
        A = v + (long)kz * 1024;
        W = Wv + (long)kz * 1024 * 512;
        C = g_vpart + (long)kz * VSUM_ELEMS;
        lda = 32768; ldc = 512; nChunks = 32; np3 = false;
    }

    int wm0 = (warp >> 2) * 64;
    int wn0 = (warp & 3) * 32;
    int g8 = lane >> 2, tq = lane & 3;

    int lrow = ((lane >> 3) & 1) * 8 + (lane & 7);
    int lk16 = ((lane >> 4) & 1) * 16;
    uint32_t aLane = sb + AOFF + (uint32_t)(wm0 + lrow) * APITCH_B + lk16;
    uint32_t bLane = sb + BOFF + (uint32_t)lrow * BPITCH_B + (uint32_t)(wn0 + ((lane >> 4) & 1) * 8) * 2;

    int am = tid >> 3, akf = (tid & 7) * 4;
    const float* Aload = A + (bm + am) * lda + akf;

    float acc[4][4][4];
#pragma unroll
    for (int mi = 0; mi < 4; mi++)
#pragma unroll
        for (int ni = 0; ni < 4; ni++)
#pragma unroll
            for (int c = 0; c < 4; c++) acc[mi][ni][c] = 0.f;

    float4 ra[4], rb[4];

#define LOADG(kb)                                                              \
    do {                                                                       \
        _Pragma("unroll")                                                      \
        for (int i = 0; i < 4; i++) {                                          \
            ra[i] = *(const float4*)(Aload + (long)(i * 32) * lda + (kb));     \
            int lin = tid + i * 256;                                           \
            int kk = lin >> 5, nf = lin & 31;                                  \
            rb[i] = *(const float4*)(W + ((kb) + kk) * 512 + n0 + nf * 4);     \
        }                                                                      \
    } while (0)

#define STORE(buf)                                                             \
    do {                                                                       \
        char* bp = smc + (buf) * BUFSZ;                                        \
        _Pragma("unroll")                                                      \
        for (int i = 0; i < 4; i++) {                                          \
            char* ap = bp + AOFF + (am + i * 32) * APITCH_B + akf * 2;         \
            int lin = tid + i * 256;                                           \
            int kk = lin >> 5, nf = lin & 31;                                  \
            char* wp = bp + BOFF + kk * BPITCH_B + nf * 8;                     \
            if (np3) {                                                         \
                uint2 hw, mw;                                                  \
                split2_pack(ra[i], hw, mw);                                    \
                *(uint2*)ap = hw; *(uint2*)(ap + APL) = mw;                    \
                split2_pack(rb[i], hw, mw);                                    \
                *(uint2*)wp = hw; *(uint2*)(wp + BPL) = mw;                    \
            } else {                                                           \
                *(uint2*)ap = f16_pack(ra[i]);                                 \
                *(uint2*)wp = f16_pack(rb[i]);                                 \
            }                                                                  \
        }                                                                      \
    } while (0)

    LOADG(0);
    STORE(0);
    if (nChunks > 1) LOADG(32);
    __syncthreads();

    for (int kt = 0; kt < nChunks; kt++) {
        int cur = kt & 1;
        if (kt + 1 < nChunks) {
            STORE(cur ^ 1);
            if (kt + 2 < nChunks) LOADG((long)(kt + 2) * 32);
        }
        uint32_t bufOff = (uint32_t)cur * BUFSZ;
#pragma unroll
        for (int ks = 0; ks < 2; ks++) {
            uint32_t Ah[4][4], Am[4][4];
#pragma unroll
            for (int mt = 0; mt < 4; mt++) {
                uint32_t ad = aLane + bufOff + mt * (16 * APITCH_B) + ks * 32;
                ldm_x4(Ah[mt], ad);
                if (np3) ldm_x4(Am[mt], ad + APL);
            }
            uint32_t Bh[4][2], Bm[4][2];
#pragma unroll
            for (int pr = 0; pr < 2; pr++) {
                uint32_t bd = bLane + bufOff + ks * (16 * BPITCH_B) + pr * 32;
                uint32_t r4[4];
                ldm_x4t(r4, bd);
                Bh[2 * pr][0] = r4[0]; Bh[2 * pr][1] = r4[1];
                Bh[2 * pr + 1][0] = r4[2]; Bh[2 * pr + 1][1] = r4[3];
                if (np3) {
                    ldm_x4t(r4, bd + BPL);
                    Bm[2 * pr][0] = r4[0]; Bm[2 * pr][1] = r4[1];
                    Bm[2 * pr + 1][0] = r4[2]; Bm[2 * pr + 1][1] = r4[3];
                }
            }
            if (np3) {
#pragma unroll
                for (int mt = 0; mt < 4; mt++)
#pragma unroll
                    for (int nt = 0; nt < 4; nt++) {
                        MMA_BF(Am, Bh, mt, nt);
                        MMA_BF(Ah, Bm, mt, nt);
                        MMA_BF(Ah, Bh, mt, nt);
                    }
            } else {
#pragma unroll
                for (int mt = 0; mt < 4; mt++)
#pragma unroll
                    for (int nt = 0; nt < 4; nt++)
                        MMA_F16(Ah, Bh, mt, nt);
            }
        }
        __syncthreads();
    }
#undef LOADG
#undef STORE

#pragma unroll
    for (int mt = 0; mt < 4; mt++) {
        long r0 = bm + wm0 + mt * 16 + g8;
#pragma unroll
        for (int nt = 0; nt < 4; nt++) {
            long c0 = n0 + wn0 + nt * 8 + 2 * tq;
            *(float2*)(C + r0 * ldc + c0) = make_float2(acc[mt][nt][0], acc[mt][nt][1]);
            *(float2*)(C + (r0 + 8) * ldc + c0) = make_float2(acc[mt][nt][2], acc[mt][nt][3]);
        }
    }
}

// ---------------- split-K reduction for vsum (float2, 256 blocks) ----------------
__global__ __launch_bounds__(256) void reduce_vsum()
{
    int idx = (blockIdx.x * 256 + threadIdx.x) * 2;
    float2 s = make_float2(0.f, 0.f);
#pragma unroll
    for (int i = 0; i < VSPLIT; i++) {
        float2 p = *(const float2*)&g_vpart[(long)i * VSUM_ELEMS + idx];
        s.x += p.x; s.y += p.y;
    }
    *(float2*)&g_vsum[idx] = s;
}

// ---------------- attention weights (MMA-based scores) ----------------
__global__ __launch_bounds__(256) void attn_kernel()
{
    __shared__ __align__(16) unsigned short Qh[64 * 72], Qm[64 * 72];
    __shared__ __align__(16) unsigned short Kh[64 * 72], Km[64 * 72];
    __shared__ float colmax[2][64];
    __shared__ float ev[64], av[64], wv[64];
    __shared__ float red[2], red2[2];
    __shared__ int cntS[4][64];
    __shared__ float dsh;
    int h = blockIdx.x, b = blockIdx.y;
    int t = threadIdx.x, lane = t & 31, w = t >> 5;

    const float* qpB = g_qp + (long)b * 64 * 512 + h * 64;
    const float* kpB = g_kp + (long)b * 64 * 512 + h * 64;
#pragma unroll
    for (int i = 0; i < 4; i++) {
        int idx = t + i * 256;
        int r = idx >> 4, c4 = (idx & 15) * 4;
        float4 qv = *(const float4*)(qpB + (long)r * 512 + c4);
        float4 kv = *(const float4*)(kpB + (long)r * 512 + c4);
        uint2 hw, mw;
        split2_pack(qv, hw, mw);
        *(uint2*)&Qh[r * 72 + c4] = hw;
        *(uint2*)&Qm[r * 72 + c4] = mw;
        split2_pack(kv, hw, mw);
        *(uint2*)&Kh[r * 72 + c4] = hw;
        *(uint2*)&Km[r * 72 + c4] = mw;
    }
    __syncthreads();

    int wr = w & 3, wc = w >> 2;
    int r0 = wr * 16, n0 = wc * 32;
    int am_row = r0 + ((lane >> 3) & 1) * 8 + (lane & 7);
    int am_col = (lane >> 4) * 16;
    uint32_t aQh = smem_u32(Qh) + am_row * 144 + am_col;
    uint32_t aQm = smem_u32(Qm) + am_row * 144 + am_col;
    int sel = (lane >> 3) & 3;
    int brow = (sel >> 1) * 8 + (lane & 7);
    int bcol = (sel & 1) * 16;
    uint32_t aKh = smem_u32(Kh) + bcol;
    uint32_t aKm = smem_u32(Km) + bcol;

    float acc[4][4];
#pragma unroll
    for (int i = 0; i < 4; i++)
#pragma unroll
        for (int j = 0; j < 4; j++) acc[i][j] = 0.f;

#pragma unroll
    for (int ks = 0; ks < 4; ks++) {
        uint32_t Ah[4], Am[4];
        ldm_x4(Ah, aQh + ks * 32);
        ldm_x4(Am, aQm + ks * 32);
#pragma unroll
        for (int ntp = 0; ntp < 2; ntp++) {
            uint32_t off = (uint32_t)(n0 + ntp * 16 + brow) * 144 + ks * 32;
            uint32_t r4[4];
            uint32_t Bh[2][2], Bm[2][2];
            ldm_x4(r4, aKh + off);
            Bh[0][0] = r4[0]; Bh[0][1] = r4[1]; Bh[1][0] = r4[2]; Bh[1][1] = r4[3];
            ldm_x4(r4, aKm + off);
            Bm[0][0] = r4[0]; Bm[0][1] = r4[1]; Bm[1][0] = r4[2]; Bm[1][1] = r4[3];
#pragma unroll
            for (int j = 0; j < 2; j++) {
                int nt = ntp * 2 + j;
                asm volatile(
                    "mma.sync.aligned.m16n8k16.row.col.f32.bf16.bf16.f32 "
                    "{%0,%1,%2,%3}, {%4,%5,%6,%7}, {%8,%9}, {%0,%1,%2,%3};"
                    : "+f"(acc[nt][0]), "+f"(acc[nt][1]), "+f"(acc[nt][2]), "+f"(acc[nt][3])
                    : "r"(Am[0]), "r"(Am[1]), "r"(Am[2]), "r"(Am[3]),
                      "r"(Bh[j][0]), "r"(Bh[j][1]));
                asm volatile(
                    "mma.sync.aligned.m16n8k16.row.col.f32.bf16.bf16.f32 "
                    "{%0,%1,%2,%3}, {%4,%5,%6,%7}, {%8,%9}, {%0,%1,%2,%3};"
                    : "+f"(acc[nt][0]), "+f"(acc[nt][1]), "+f"(acc[nt][2]), "+f"(acc[nt][3])
                    : "r"(Ah[0]), "r"(Ah[1]), "r"(Ah[2]), "r"(Ah[3]),
                      "r"(Bm[j][0]), "r"(Bm[j][1]));
                asm volatile(
                    "mma.sync.aligned.m16n8k16.row.col.f32.bf16.bf16.f32 "
                    "{%0,%1,%2,%3}, {%4,%5,%6,%7}, {%8,%9}, {%0,%1,%2,%3};"
                    : "+f"(acc[nt][0]), "+f"(acc[nt][1]), "+f"(acc[nt][2]), "+f"(acc[nt][3])
                    : "r"(Ah[0]), "r"(Ah[1]), "r"(Ah[2]), "r"(Ah[3]),
                      "r"(Bh[j][0]), "r"(Bh[j][1]));
            }
        }
    }

    float m1 = acc[0][0], m2 = acc[0][2];
#pragma unroll
    for (int nt = 0; nt < 4; nt++) {
        m1 = fmaxf(m1, fmaxf(acc[nt][0], acc[nt][1]));
        m2 = fmaxf(m2, fmaxf(acc[nt][2], acc[nt][3]));
    }
    m1 = fmaxf(m1, __shfl_xor_sync(0xffffffffu, m1, 1));
    m1 = fmaxf(m1, __shfl_xor_sync(0xffffffffu, m1, 2));
    m2 = fmaxf(m2, __shfl_xor_sync(0xffffffffu, m2, 1));
    m2 = fmaxf(m2, __shfl_xor_sync(0xffffffffu, m2, 2));
    if ((lane & 3) == 0) {
        colmax[wc][r0 + (lane >> 2)] = m1;
        colmax[wc][r0 + (lane >> 2) + 8] = m2;
    }
    __syncthreads();
    if (t < 64) ev[t] = expf(fmaxf(colmax[0][t], colmax[1][t]) * 0.125f);
    __syncthreads();

    if (t < 64) {
        float m = ev[t];
#pragma unroll
        for (int s = 16; s > 0; s >>= 1) m = fmaxf(m, __shfl_xor_sync(0xffffffffu, m, s));
        if (lane == 0) red[w] = m;
    }
    __syncthreads();
    if (t < 64) {
        float m = fmaxf(red[0], red[1]);
        float sx = expf(ev[t] - m);
        av[t] = sx;
        float ss = sx;
#pragma unroll
        for (int s = 16; s > 0; s >>= 1) ss += __shfl_xor_sync(0xffffffffu, ss, s);
        if (lane == 0) red2[w] = ss;
    }
    __syncthreads();
    if (t < 64) av[t] = av[t] / (red2[0] + red2[1]);
    __syncthreads();

    {
        int r = t & 63, part = t >> 6;
        float ar = av[r];
        int cnt = 0;
        int j0 = part * 16;
#pragma unroll
        for (int j = 0; j < 16; j++) {
            float o = av[j0 + j];
            cnt += (o > ar) || (o == ar && (j0 + j) < r);
        }
        cntS[part][r] = cnt;
    }
    __syncthreads();
    if (t < 64) {
        int cnt = cntS[0][t] + cntS[1][t] + cntS[2][t] + cntS[3][t];
        if (cnt == TOPKK - 1) dsh = av[t];
    }
    __syncthreads();
    if (t < 64) {
        float wq = fmaxf(av[t] - (dsh + EPSF), 0.f);
        wv[t] = wq;
        float ws = wq;
#pragma unroll
        for (int s = 16; s > 0; s >>= 1) ws += __shfl_xor_sync(0xffffffffu, ws, s);
        if (lane == 0) red[w] = ws;
    }
    __syncthreads();
    if (t < 64)
        g_attn[((long)b * 64 + t) * 8 + h] = wv[t] / (red[0] + red[1] + EPSF);
}

// ---------------- F/G via f16 mma: per head (256b x 64d) @ W_h^T (64d x 512o) ----------------
// grid (NH, 2 m-tiles of 128 b, 8 n-tiles: z<4 -> F cols z*128, z>=4 -> G cols (z-4)*128)
#define FG_AP 144   /* 64 f16 = 128B payload + 16B pad (was 80: row overlap bug) */
#define FG_BP 144
__global__ __launch_bounds__(256) void fg_mma(const float* __restrict__ fc_w,
                                              const float* __restrict__ gate_w)
{
    __shared__ __align__(16) char As[128 * FG_AP];   /* 18432 */
    __shared__ __align__(16) char Bs[128 * FG_BP];   /* 18432 */
    int h = blockIdx.x;
    int b0 = blockIdx.y * 128;
    int zn = blockIdx.z;
    const float* Wsel = (zn < 4) ? fc_w : gate_w;
    float* Out = (zn < 4) ? g_F : g_G;
    int o0 = (zn & 3) * 128;
    int tid = threadIdx.x, lane = tid & 31, warp = tid >> 5;

#pragma unroll
    for (int i = 0; i < 8; i++) {
        int lin = tid + i * 256;
        int r = lin >> 4, c4 = (lin & 15) * 4;
        float4 av = *(const float4*)&g_vsum[(long)(b0 + r) * 512 + h * 64 + c4];
        *(uint2*)(As + r * FG_AP + c4 * 2) = f16_pack(av);
        float4 bv = *(const float4*)&Wsel[(long)(o0 + r) * 512 + h * 64 + c4];
        *(uint2*)(Bs + r * FG_BP + c4 * 2) = f16_pack(bv);
    }
    __syncthreads();

    int wm0 = (warp >> 2) * 64, wn0 = (warp & 3) * 32;
    int g8 = lane >> 2, tq = lane & 3;
    int arow = ((lane >> 3) & 1) * 8 + (lane & 7);
    int acol = (lane >> 4) * 16;
    uint32_t aBase = smem_u32(As) + (uint32_t)(wm0 + arow) * FG_AP + acol;
    int sel = (lane >> 3) & 3;
    int brow = (sel >> 1) * 8 + (lane & 7);
    int bcol = (sel & 1) * 16;
    uint32_t bBase = smem_u32(Bs) + bcol;

    float acc[4][4][4];
#pragma unroll
    for (int mi = 0; mi < 4; mi++)
#pragma unroll
        for (int ni = 0; ni < 4; ni++)
#pragma unroll
            for (int c = 0; c < 4; c++) acc[mi][ni][c] = 0.f;

#pragma unroll
    for (int ks = 0; ks < 4; ks++) {
        uint32_t Af[4][4];
#pragma unroll
        for (int mt = 0; mt < 4; mt++)
            ldm_x4(Af[mt], aBase + mt * (16 * FG_AP) + ks * 32);
        uint32_t Bf[4][2];
#pragma unroll
        for (int ntp = 0; ntp < 2; ntp++) {
            uint32_t r4[4];
            ldm_x4(r4, bBase + (uint32_t)(wn0 + ntp * 16 + brow) * FG_BP + ks * 32);
            Bf[2 * ntp][0] = r4[0]; Bf[2 * ntp][1] = r4[1];
            Bf[2 * ntp + 1][0] = r4[2]; Bf[2 * ntp + 1][1] = r4[3];
        }
#pragma unroll
        for (int mt = 0; mt < 4; mt++)
#pragma unroll
            for (int nt = 0; nt < 4; nt++)
                MMA_F16(Af, Bf, mt, nt);
    }

#pragma unroll
    for (int mt = 0; mt < 4; mt++) {
        int br = b0 + wm0 + mt * 16 + g8;
#pragma unroll
        for (int nt = 0; nt < 4; nt++) {
            int col = o0 + wn0 + nt * 8 + 2 * tq;
            *(float2*)&Out[((long)br * 8 + h) * 512 + col] =
                make_float2(acc[mt][nt][0], acc[mt][nt][1]);
            *(float2*)&Out[((long)(br + 8) * 8 + h) * 512 + col] =
                make_float2(acc[mt][nt][2], acc[mt][nt][3]);
        }
    }
}

// ---------------- final gated combine ----------------
__global__ __launch_bounds__(256) void final_kernel(const float* __restrict__ fc_b,
                                                    const float* __restrict__ gate_b,
                                                    float* __restrict__ out)
{
    __shared__ float aw[64][8];
    __shared__ float Fs[8][128];
    __shared__ float Gs[8][128];
    __shared__ float fb[128], gb[128];
    int o0 = blockIdx.x * 128;
    int b = blockIdx.y;
    int t = threadIdx.x;

    for (int i = t; i < 512; i += 256)
        ((float*)aw)[i] = g_attn[(long)b * 512 + i];
    for (int i = t; i < 1024; i += 256) {
        int h = i >> 7, o = i & 127;
        Fs[h][o] = g_F[((long)b * 8 + h) * 512 + o0 + o];
        Gs[h][o] = g_G[((long)b * 8 + h) * 512 + o0 + o];
    }
    if (t < 128) {
        fb[t] = fc_b[o0 + t];
        gb[t] = gate_b[o0 + t];
    }
    __syncthreads();

    int oc = t & 31, rw = t >> 5;
    for (int r = rw; r < 64; r += 8) {
        float ah[8];
#pragma unroll
        for (int h = 0; h < 8; h++) ah[h] = aw[r][h];
        for (int ob = 0; ob < 128; ob += 32) {
            int o = ob + oc;
            float f = fb[o], g = gb[o];
#pragma unroll
            for (int h = 0; h < 8; h++) {
                f = fmaf(ah[h], Fs[h][o], f);
                g = fmaf(ah[h], Gs[h][o], g);
            }
            float sg = 1.f / (1.f + expf(-g));
            out[((long)b * 64 + r) * 512 + o0 + o] = sg * tanhf(f);
        }
    }
}

// ---------------- launch ----------------
extern "C" void kernel_launch(void* const* d_in, const int* in_sizes, int n_in,
                              void* d_out, int out_size)
{
    const float* q      = (const float*)d_in[0];
    const float* k      = (const float*)d_in[1];
    const float* v      = (const float*)d_in[2];
    const float* Wq     = (const float*)d_in[3];
    const float* Wk     = (const float*)d_in[4];
    const float* Wv     = (const float*)d_in[5];
    const float* fc_w   = (const float*)d_in[6];
    const float* fc_b   = (const float*)d_in[7];
    const float* gate_w = (const float*)d_in[8];
    const float* gate_b = (const float*)d_in[9];
    float* out = (float*)d_out;
    (void)in_sizes; (void)n_in; (void)out_size;

    cudaFuncSetAttribute(gemm_mma, cudaFuncAttributeMaxDynamicSharedMemorySize,
                         GEMM_SMEM);

    // z<64 qproj (bf16x3), z<128 kproj (bf16x3), z>=128 vsum split-K (f16x1)
    gemm_mma<<<dim3(4, 2, 160), 256, GEMM_SMEM>>>(q, k, v, Wq, Wk, Wv);
    reduce_vsum<<<VSUM_ELEMS / 512, 256>>>();

    attn_kernel<<<dim3(NH, Bb), 256>>>();
    fg_mma<<<dim3(NH, 2, 8), 256>>>(fc_w, gate_w);
    final_kernel<<<dim3(4, Bb), 256>>>(fc_b, gate_b, out);
}